// round 11
// baseline (speedup 1.0000x reference)
#include <cuda_runtime.h>
#include <cuda_fp16.h>
#include <math.h>
#include <stdint.h>

#define NN 50000
#define EE 800000
#define FF 256
#define NF (NN*FF)            // 12,800,000
#define EF (EE*FF)            // 204,800,000
#define LL 4
#define WK 256                // weight: single fp16 [N=256, K=256] K-major
#define WSZ (256*WK)

// GEMM tiling: BM=128, BN=256, BK=64, 512 threads (16 warps, 4x4)
#define BM 128
#define AST 72
#define BST 72
#define ABYTES (BM*AST*2)      // 18432
#define BBYTES (256*BST*2)     // 36864
#define BUFB (ABYTES + BBYTES) // 55296
#define SMEMB (2*BUFB)         // 110592

// ------------------------- scratch (device globals, no allocs) -------------
__device__ __half g_etmp[EF];      // fp16 e_tmp
__device__ __half g_hW[5*NF];      // fp16: hWs | hWd | hself | hWf | hWb
__device__ float g_htmp[NF];
__device__ float g_logf[EE];
__device__ float g_logb[EE];
__device__ float g_exf[EE];
__device__ float g_exb[EE];
__device__ float g_mf[NN];
__device__ float g_mb[NN];
__device__ float g_denf[NN];
__device__ float g_denb[NN];
__device__ float g_cols[8*FF];
__device__ __half g_hhi[NF];
__device__ __half g_hlo[NF];
__device__ __half g_ehi[EF];
__device__ __half g_elo[EF];
__device__ __half g_Wt[LL*6*WSZ];
__device__ float g_dumpE[EF];      // fallback-only fp32 sink
// CSR
__device__ int g_degf[NN];
__device__ int g_degb[NN];
__device__ int g_offf[NN+1];
__device__ int g_offb[NN+1];
__device__ int g_idxf[EE];
__device__ int g_idxb[EE];

// ------------------------- helpers -----------------------------------------
__device__ __forceinline__ uint32_t s2u(const void* p) {
    uint32_t a;
    asm("{ .reg .u64 t; cvta.to.shared.u64 t, %1; cvt.u32.u64 %0, t; }" : "=r"(a) : "l"(p));
    return a;
}
__device__ __forceinline__ void cp_async16(uint32_t saddr, const void* g) {
    asm volatile("cp.async.cg.shared.global [%0], [%1], 16;" :: "r"(saddr), "l"(g));
}
__device__ __forceinline__ void ldsm4(uint32_t addr, uint32_t& r0, uint32_t& r1,
                                      uint32_t& r2, uint32_t& r3) {
    asm volatile("ldmatrix.sync.aligned.m8n8.x4.shared.b16 {%0,%1,%2,%3}, [%4];"
                 : "=r"(r0), "=r"(r1), "=r"(r2), "=r"(r3) : "r"(addr));
}
__device__ __forceinline__ void mma16816(float* d, const uint32_t* a, const uint32_t* b) {
    asm volatile(
        "mma.sync.aligned.m16n8k16.row.col.f32.f16.f16.f32 "
        "{%0,%1,%2,%3}, {%4,%5,%6,%7}, {%8,%9}, {%0,%1,%2,%3};"
        : "+f"(d[0]), "+f"(d[1]), "+f"(d[2]), "+f"(d[3])
        : "r"(a[0]), "r"(a[1]), "r"(a[2]), "r"(a[3]), "r"(b[0]), "r"(b[1]));
}
__device__ __forceinline__ void atomicMaxF(float* a, float v) {
    int* ai = (int*)a;
    int old = __float_as_int(*a);
    while (__int_as_float(old) < v) {
        int prev = atomicCAS(ai, old, __float_as_int(v));
        if (prev == old) break;
        old = prev;
    }
}

// ------------------------- fp16 mma GEMM ------------------------------------
// C(fp16)[tile*128..+128, 0..256) = A@W.
// TERMS=2: hi/lo split over 8 chunks; TERMS=1: hi only, 4 chunks.
// EDGE: adds gs[src]+gd[dst] (fp16) in epilogue, then attention logits
// (+segment max) and BN column stats in fp32 (fused); stores C as fp16.
template<bool EDGE, int TERMS>
__device__ __forceinline__ void mma_gemm(
    const __half* __restrict__ Ahi, const __half* __restrict__ Alo,
    const __half* __restrict__ Bt, __half* __restrict__ C, int M, int tile,
    const int* __restrict__ src, const int* __restrict__ dst,
    const __half* __restrict__ gs, const __half* __restrict__ gd,
    const float* __restrict__ af, const float* __restrict__ ab,
    float* __restrict__ logf, float* __restrict__ logb,
    float* __restrict__ mf, float* __restrict__ mb,
    float* __restrict__ cse, float* __restrict__ cqe)
{
    extern __shared__ __align__(16) char smem[];
    const uint32_t sb = s2u(smem);
    const int tid = threadIdx.x, wid = tid >> 5, lane = tid & 31;
    const int m0 = tile * BM;
    const int NC = 4 * TERMS;

    auto load_chunk = [&](int c, int buf) {
        int g = (TERMS == 2) ? (c >> 1) : c;
        int t = (TERMS == 2) ? (c & 1) : 0;
        const __half* As = t ? Alo : Ahi;
        const int acol = g << 6;
        const int kb = g << 6;
        const uint32_t a_s = sb + buf*BUFB;
        const uint32_t b_s = a_s + ABYTES;
        #pragma unroll
        for (int i = 0; i < 2; i++) {            // A: 128x64 halves
            int v = tid + (i << 9); int r = v >> 3, c16 = v & 7;
            uint32_t sa = a_s + (r*AST + (c16 << 3))*2;
            int gr = m0 + r;
            if (EDGE) {
                cp_async16(sa, As + (size_t)gr*256 + acol + (c16 << 3));
            } else {
                if (gr < M) cp_async16(sa, As + (size_t)gr*256 + acol + (c16 << 3));
                else asm volatile("st.shared.v4.b32 [%0], {%1,%1,%1,%1};" :: "r"(sa), "r"(0));
            }
        }
        #pragma unroll
        for (int i = 0; i < 4; i++) {            // B: 256x64 halves
            int v = tid + (i << 9); int r = v >> 3, c16 = v & 7;
            cp_async16(b_s + (r*BST + (c16 << 3))*2, Bt + r*WK + kb + (c16 << 3));
        }
        asm volatile("cp.async.commit_group;");
    };

    const int wm = (wid & 3) << 5;               // 0..96
    const int wn = (wid >> 2) << 6;              // 0,64,128,192
    uint32_t a_off[2];
    #pragma unroll
    for (int im = 0; im < 2; im++)
        a_off[im] = ((wm + im*16 + (lane & 15))*AST + ((lane >> 4) << 3))*2;
    const uint32_t b_off = ((wn + ((lane >> 4) << 3) + (lane & 7))*BST
                           + (((lane >> 3) & 1) << 3))*2;

    float acc[2][8][4];
    #pragma unroll
    for (int im = 0; im < 2; im++)
        #pragma unroll
        for (int j = 0; j < 8; j++)
            #pragma unroll
            for (int q = 0; q < 4; q++) acc[im][j][q] = 0.f;

    load_chunk(0, 0);
    int buf = 0;
    for (int c = 0; c < NC; c++) {
        if (c < NC-1) {
            load_chunk(c + 1, buf ^ 1);
            asm volatile("cp.async.wait_group 1;");
        } else {
            asm volatile("cp.async.wait_group 0;");
        }
        __syncthreads();
        const uint32_t a_s = sb + buf*BUFB;
        const uint32_t b_s = a_s + ABYTES;
        #pragma unroll
        for (int ks = 0; ks < 4; ks++) {
            const uint32_t kh2 = (ks << 4)*2;
            uint32_t a[2][4], b[8][2];
            ldsm4(a_s + a_off[0] + kh2, a[0][0], a[0][1], a[0][2], a[0][3]);
            ldsm4(a_s + a_off[1] + kh2, a[1][0], a[1][1], a[1][2], a[1][3]);
            #pragma unroll
            for (int jp = 0; jp < 4; jp++)
                ldsm4(b_s + b_off + jp*(16*BST*2) + kh2,
                      b[2*jp][0], b[2*jp][1], b[2*jp+1][0], b[2*jp+1][1]);
            #pragma unroll
            for (int im = 0; im < 2; im++)
                #pragma unroll
                for (int j = 0; j < 8; j++)
                    mma16816(acc[im][j], a[im], b[j]);
        }
        __syncthreads();
        buf ^= 1;
    }

    // ---------------- epilogue ----------------
    const int gr0 = lane >> 2;
    const int cl0 = (lane & 3) << 1;

    if (!EDGE) {
        #pragma unroll
        for (int im = 0; im < 2; im++)
            #pragma unroll
            for (int half = 0; half < 2; half++) {
                int gm = m0 + wm + im*16 + gr0 + half*8;
                if (gm >= M) continue;
                #pragma unroll
                for (int j = 0; j < 8; j++) {
                    int col = wn + (j << 3) + cl0;
                    *(__half2*)(C + (size_t)gm*256 + col) =
                        __float22half2_rn(make_float2(acc[im][j][half*2], acc[im][j][half*2+1]));
                }
            }
        return;
    }

    // EDGE: fused gather + logits + BN stats
    float* sred = (float*)smem;   // [0:128) rowf | [128:256) rowb | [256:512) cs | [512:768) cq
    for (int i = tid; i < 768; i += 512) sred[i] = 0.f;
    __syncthreads();

    float cs[16], cq[16];
    #pragma unroll
    for (int q = 0; q < 16; q++) { cs[q] = 0.f; cq[q] = 0.f; }

    #pragma unroll
    for (int im = 0; im < 2; im++)
        #pragma unroll
        for (int half = 0; half < 2; half++) {
            int rloc = wm + im*16 + gr0 + half*8;
            int gm = m0 + rloc;
            int s = src[gm], d = dst[gm];
            float pf = 0.f, pb = 0.f;
            #pragma unroll
            for (int j = 0; j < 8; j++) {
                int col = wn + (j << 3) + cl0;
                float2 o = make_float2(acc[im][j][half*2], acc[im][j][half*2+1]);
                float2 x = __half22float2(*(const __half2*)(gs + (size_t)s*256 + col));
                float2 y = __half22float2(*(const __half2*)(gd + (size_t)d*256 + col));
                o.x += x.x + y.x; o.y += x.y + y.y;
                *(__half2*)(C + (size_t)gm*256 + col) = __float22half2_rn(o);
                pf += o.x*__ldg(af+col) + o.y*__ldg(af+col+1);
                pb += o.x*__ldg(ab+col) + o.y*__ldg(ab+col+1);
                cs[j*2]   += o.x; cs[j*2+1] += o.y;
                cq[j*2]   += o.x*o.x; cq[j*2+1] += o.y*o.y;
            }
            pf += __shfl_xor_sync(0xFFFFFFFFu, pf, 1);
            pf += __shfl_xor_sync(0xFFFFFFFFu, pf, 2);
            pb += __shfl_xor_sync(0xFFFFFFFFu, pb, 1);
            pb += __shfl_xor_sync(0xFFFFFFFFu, pb, 2);
            if ((lane & 3) == 0) {
                atomicAdd(&sred[rloc], pf);
                atomicAdd(&sred[128 + rloc], pb);
            }
        }
    #pragma unroll
    for (int q = 0; q < 16; q++) {
        cs[q] += __shfl_xor_sync(0xFFFFFFFFu, cs[q], 4);
        cs[q] += __shfl_xor_sync(0xFFFFFFFFu, cs[q], 8);
        cs[q] += __shfl_xor_sync(0xFFFFFFFFu, cs[q], 16);
        cq[q] += __shfl_xor_sync(0xFFFFFFFFu, cq[q], 4);
        cq[q] += __shfl_xor_sync(0xFFFFFFFFu, cq[q], 8);
        cq[q] += __shfl_xor_sync(0xFFFFFFFFu, cq[q], 16);
    }
    if (lane < 4) {
        #pragma unroll
        for (int j = 0; j < 8; j++) {
            int col = wn + (j << 3) + ((lane & 3) << 1);
            atomicAdd(&sred[256 + col],     cs[j*2]);
            atomicAdd(&sred[256 + col + 1], cs[j*2+1]);
            atomicAdd(&sred[512 + col],     cq[j*2]);
            atomicAdd(&sred[512 + col + 1], cq[j*2+1]);
        }
    }
    __syncthreads();
    if (tid < 128) {
        int gm = m0 + tid;
        float lf = sred[tid];       lf = lf > 0.f ? lf : 0.2f*lf;
        float lb = sred[128 + tid]; lb = lb > 0.f ? lb : 0.2f*lb;
        logf[gm] = lf; logb[gm] = lb;
        atomicMaxF(&mf[dst[gm]], lf);
        atomicMaxF(&mb[src[gm]], lb);
    } else if (tid < 384) {
        int col = tid - 128;
        atomicAdd(&cse[col], sred[256 + col]);
        atomicAdd(&cqe[col], sred[512 + col]);
    }
}

struct O5 { __half* O[5]; };

__global__ __launch_bounds__(512)
void node_mma_k(const __half* __restrict__ Ahi, const __half* __restrict__ Alo,
                const __half* __restrict__ WtL, O5 p, int M) {
    mma_gemm<false, 2>(Ahi, Alo, WtL + (size_t)(blockIdx.z + 1)*WSZ, p.O[blockIdx.z],
                       M, blockIdx.x, nullptr, nullptr, nullptr, nullptr,
                       nullptr, nullptr, nullptr, nullptr, nullptr, nullptr, nullptr, nullptr);
}

__global__ __launch_bounds__(512)
void edge_mma_k(const __half* __restrict__ Ahi,
                const __half* __restrict__ WtL, __half* __restrict__ C,
                const int* __restrict__ src, const int* __restrict__ dst,
                const __half* __restrict__ gs, const __half* __restrict__ gd,
                const float* __restrict__ af, const float* __restrict__ ab,
                float* __restrict__ logf, float* __restrict__ logb,
                float* __restrict__ mf, float* __restrict__ mb,
                float* __restrict__ cse, float* __restrict__ cqe) {
    mma_gemm<true, 1>(Ahi, Ahi, WtL, C, EE, blockIdx.x, src, dst, gs, gd,
                      af, ab, logf, logb, mf, mb, cse, cqe);
}

// ------------------------- prep / CSR ---------------------------------------
struct W6 { const float* p[6]; };

// Wt[l][w][n][k] fp16, K-major
__global__ void prep_w_k(W6 w, __half* __restrict__ out) {
    long idx = (long)blockIdx.x * 256 + threadIdx.x;      // LL*6*256*256
    int k = (int)(idx % WK); long t = idx / WK;
    int n = (int)(t % 256);  t /= 256;
    int wi = (int)(t % 6);   int l = (int)(t / 6);
    out[idx] = __float2half(w.p[wi][((size_t)l * 256 + k) * 256 + n]);
}

__global__ void cvt_k(const float4* __restrict__ x, __half2* __restrict__ hi,
                      __half2* __restrict__ lo, int n4) {
    int i = blockIdx.x * blockDim.x + threadIdx.x;
    if (i >= n4) return;
    float4 v = x[i];
    __half h0 = __float2half(v.x), h1 = __float2half(v.y);
    __half h2 = __float2half(v.z), h3 = __float2half(v.w);
    hi[2*i]   = __halves2half2(h0, h1);
    hi[2*i+1] = __halves2half2(h2, h3);
    lo[2*i]   = __halves2half2(__float2half(v.x - __half2float(h0)),
                               __float2half(v.y - __half2float(h1)));
    lo[2*i+1] = __halves2half2(__float2half(v.z - __half2float(h2)),
                               __float2half(v.w - __half2float(h3)));
}

__global__ void zero_deg_k(int* df, int* db) {
    int i = blockIdx.x*blockDim.x + threadIdx.x;
    if (i < NN) { df[i] = 0; db[i] = 0; }
}
__global__ void hist_k(const int* __restrict__ src, const int* __restrict__ dst,
                       int* df, int* db) {
    int e = blockIdx.x*blockDim.x + threadIdx.x;
    if (e >= EE) return;
    atomicAdd(&df[dst[e]], 1);
    atomicAdd(&db[src[e]], 1);
}
__global__ void scan_k(const int* __restrict__ degf, const int* __restrict__ degb,
                       int* offf, int* offb) {
    __shared__ int s[1024];
    for (int arr = 0; arr < 2; arr++) {
        const int* deg = arr ? degb : degf;
        int* off = arr ? offb : offf;
        int carry = 0;
        if (threadIdx.x == 0) off[0] = 0;
        for (int base = 0; base < NN; base += 1024) {
            int i = base + threadIdx.x;
            s[threadIdx.x] = (i < NN) ? deg[i] : 0;
            __syncthreads();
            for (int d = 1; d < 1024; d <<= 1) {
                int t = (threadIdx.x >= d) ? s[threadIdx.x - d] : 0;
                __syncthreads();
                s[threadIdx.x] += t;
                __syncthreads();
            }
            if (i < NN) off[i+1] = carry + s[threadIdx.x];
            carry += s[1023];
            __syncthreads();
        }
    }
}
__global__ void curcpy_k(const int* offf, const int* offb, int* curf, int* curb) {
    int i = blockIdx.x*blockDim.x + threadIdx.x;
    if (i < NN) { curf[i] = offf[i]; curb[i] = offb[i]; }
}
__global__ void fill_k(const int* __restrict__ src, const int* __restrict__ dst,
                       int* curf, int* curb, int* idxf, int* idxb) {
    int e = blockIdx.x*blockDim.x + threadIdx.x;
    if (e >= EE) return;
    idxf[atomicAdd(&curf[dst[e]], 1)] = e;
    idxb[atomicAdd(&curb[src[e]], 1)] = e;
}

// ------------------------- per-layer small kernels --------------------------
__global__ void init_k(float* mf, float* mb, float* denf, float* denb, float* cols) {
    int i = blockIdx.x*blockDim.x + threadIdx.x;
    if (i < NN) { mf[i] = -INFINITY; mb[i] = -INFINITY; denf[i] = 0.f; denb[i] = 0.f; }
    if (i < 8*FF) cols[i] = 0.f;
}

__global__ void finalize_bn_k(const float* __restrict__ colsum, const float* __restrict__ colsumsq,
                              const float* __restrict__ g, const float* __restrict__ b,
                              float invM, float* __restrict__ scale, float* __restrict__ shift) {
    int f = threadIdx.x;
    float mean = colsum[f] * invM;
    float var  = colsumsq[f] * invM - mean*mean;
    float sc   = g[f] * rsqrtf(var + 1e-5f);
    scale[f] = sc;
    shift[f] = b[f] - mean * sc;
}

__global__ void exp_k(const float* __restrict__ logf, const float* __restrict__ logb,
                      const int* __restrict__ src, const int* __restrict__ dst,
                      const float* __restrict__ mf, const float* __restrict__ mb,
                      float* __restrict__ exf, float* __restrict__ exb,
                      float* __restrict__ denf, float* __restrict__ denb) {
    int i = blockIdx.x*blockDim.x + threadIdx.x;
    if (i >= EE) return;
    int d = dst[i], s = src[i];
    float ef = expf(logf[i] - mf[d]);
    float eb = expf(logb[i] - mb[s]);
    exf[i] = ef; exb[i] = eb;
    atomicAdd(&denf[d], ef);
    atomicAdd(&denb[s], eb);
}

// out = (hi+lo) + relu(x*scale+shift); store back hi/lo; optional fp32 out.
// XH: x is fp16 (etmp), else fp32 (htmp).
template<bool XH>
__global__ void residual_k(__half2* hi, __half2* lo, const void* __restrict__ xv,
                           const float* __restrict__ scale, const float* __restrict__ shift,
                           float4* __restrict__ outF, int n4, int writeF) {
    int i = blockIdx.x*blockDim.x + threadIdx.x;
    if (i >= n4) return;
    int c4 = i & 63;
    __half2 a0 = hi[2*i], a1 = hi[2*i+1], b0 = lo[2*i], b1 = lo[2*i+1];
    float4 base;
    base.x = __half2float(a0.x) + __half2float(b0.x);
    base.y = __half2float(a0.y) + __half2float(b0.y);
    base.z = __half2float(a1.x) + __half2float(b1.x);
    base.w = __half2float(a1.y) + __half2float(b1.y);
    float4 v;
    if (XH) {
        const __half2* x2 = (const __half2*)xv;
        float2 u0 = __half22float2(x2[2*i]);
        float2 u1 = __half22float2(x2[2*i+1]);
        v = make_float4(u0.x, u0.y, u1.x, u1.y);
    } else {
        v = ((const float4*)xv)[i];
    }
    float4 sc = ((const float4*)scale)[c4];
    float4 sh = ((const float4*)shift)[c4];
    float4 r;
    r.x = base.x + fmaxf(v.x*sc.x + sh.x, 0.f);
    r.y = base.y + fmaxf(v.y*sc.y + sh.y, 0.f);
    r.z = base.z + fmaxf(v.z*sc.z + sh.z, 0.f);
    r.w = base.w + fmaxf(v.w*sc.w + sh.w, 0.f);
    __half h0 = __float2half(r.x), h1 = __float2half(r.y);
    __half h2 = __float2half(r.z), h3 = __float2half(r.w);
    hi[2*i]   = __halves2half2(h0, h1);
    hi[2*i+1] = __halves2half2(h2, h3);
    lo[2*i]   = __halves2half2(__float2half(r.x - __half2float(h0)),
                               __float2half(r.y - __half2float(h1)));
    lo[2*i+1] = __halves2half2(__float2half(r.z - __half2float(h2)),
                               __float2half(r.w - __half2float(h3)));
    if (writeF) outF[i] = r;
}

// CSR gather aggregation + node update + BN stats (hW inputs fp16).
__global__ void gather_node_k(
    const int* __restrict__ offf, const int* __restrict__ idxf,
    const int* __restrict__ offb, const int* __restrict__ idxb,
    const int* __restrict__ src, const int* __restrict__ dst,
    const float* __restrict__ exf, const float* __restrict__ denf,
    const float* __restrict__ exb, const float* __restrict__ denb,
    const __half2* __restrict__ hWf, const __half2* __restrict__ hWb,
    const __half2* __restrict__ hself, float4* __restrict__ htmp,
    float* __restrict__ colsum, float* __restrict__ colsumsq) {
    __shared__ float4 scs[256], scq[256];
    const int sub = threadIdx.x >> 6, c = threadIdx.x & 63;
    float4 csum = make_float4(0,0,0,0), csq = make_float4(0,0,0,0);
    #pragma unroll 1
    for (int nn = 0; nn < 8; nn++) {
        int node = blockIdx.x*32 + sub*8 + nn;
        if (node >= NN) break;
        float invf = 1.f/(denf[node] + 1e-9f);
        float invb = 1.f/(denb[node] + 1e-9f);
        float2 s0 = __half22float2(hself[(size_t)node*128 + 2*c]);
        float2 s1 = __half22float2(hself[(size_t)node*128 + 2*c + 1]);
        float4 acc = make_float4(s0.x, s0.y, s1.x, s1.y);
        int e0 = offf[node], e1 = offf[node+1];
        for (int i = e0; i < e1; i++) {
            int e = idxf[i];
            float a = exf[e]*invf;
            float2 v0 = __half22float2(hWf[(size_t)src[e]*128 + 2*c]);
            float2 v1 = __half22float2(hWf[(size_t)src[e]*128 + 2*c + 1]);
            acc.x += a*v0.x; acc.y += a*v0.y; acc.z += a*v1.x; acc.w += a*v1.y;
        }
        e0 = offb[node]; e1 = offb[node+1];
        for (int i = e0; i < e1; i++) {
            int e = idxb[i];
            float a = exb[e]*invb;
            float2 v0 = __half22float2(hWb[(size_t)dst[e]*128 + 2*c]);
            float2 v1 = __half22float2(hWb[(size_t)dst[e]*128 + 2*c + 1]);
            acc.x += a*v0.x; acc.y += a*v0.y; acc.z += a*v1.x; acc.w += a*v1.y;
        }
        htmp[(size_t)node*64 + c] = acc;
        csum.x += acc.x; csum.y += acc.y; csum.z += acc.z; csum.w += acc.w;
        csq.x += acc.x*acc.x; csq.y += acc.y*acc.y; csq.z += acc.z*acc.z; csq.w += acc.w*acc.w;
    }
    scs[threadIdx.x] = csum; scq[threadIdx.x] = csq;
    __syncthreads();
    if (sub == 0) {
        float4 s = scs[c], q = scq[c];
        #pragma unroll
        for (int k = 1; k < 4; k++) {
            float4 t = scs[k*64 + c], u = scq[k*64 + c];
            s.x += t.x; s.y += t.y; s.z += t.z; s.w += t.w;
            q.x += u.x; q.y += u.y; q.z += u.z; q.w += u.w;
        }
        atomicAdd(&colsum[c*4+0], s.x); atomicAdd(&colsum[c*4+1], s.y);
        atomicAdd(&colsum[c*4+2], s.z); atomicAdd(&colsum[c*4+3], s.w);
        atomicAdd(&colsumsq[c*4+0], q.x); atomicAdd(&colsumsq[c*4+1], q.y);
        atomicAdd(&colsumsq[c*4+2], q.z); atomicAdd(&colsumsq[c*4+3], q.w);
    }
}

// ------------------------- host orchestration ------------------------------
static float* symF(const void* s) { void* p = nullptr; cudaGetSymbolAddress(&p, s); return (float*)p; }
static int*   symI(const void* s) { void* p = nullptr; cudaGetSymbolAddress(&p, s); return (int*)p; }
static __half* symH(const void* s) { void* p = nullptr; cudaGetSymbolAddress(&p, s); return (__half*)p; }

extern "C" void kernel_launch(void* const* d_in, const int* in_sizes, int n_in,
                              void* d_out, int out_size) {
    const float* h0   = (const float*)d_in[0];
    const float* e0   = (const float*)d_in[1];
    const int*   src  = (const int*)d_in[2];
    const int*   dst  = (const int*)d_in[3];
    const float* We   = (const float*)d_in[4];
    const float* Ws   = (const float*)d_in[5];
    const float* Wd   = (const float*)d_in[6];
    const float* Wse  = (const float*)d_in[7];
    const float* Wf   = (const float*)d_in[8];
    const float* Wb   = (const float*)d_in[9];
    const float* attf = (const float*)d_in[10];
    const float* attb = (const float*)d_in[11];
    const float* ge   = (const float*)d_in[12];
    const float* be   = (const float*)d_in[13];
    const float* gh   = (const float*)d_in[14];
    const float* bh   = (const float*)d_in[15];

    __half* etmp = symH(g_etmp);
    __half* hW   = symH(g_hW);
    float* htmp = symF(g_htmp);
    float* logf = symF(g_logf);
    float* logb = symF(g_logb);
    float* exf  = symF(g_exf);
    float* exb  = symF(g_exb);
    float* mf   = symF(g_mf);
    float* mb   = symF(g_mb);
    float* denf = symF(g_denf);
    float* denb = symF(g_denb);
    float* cols = symF(g_cols);
    __half* hhi = symH(g_hhi);
    __half* hlo = symH(g_hlo);
    __half* ehi = symH(g_ehi);
    __half* elo = symH(g_elo);
    __half* Wt  = symH(g_Wt);
    int* degf = symI(g_degf);  int* degb = symI(g_degb);
    int* offf = symI(g_offf);  int* offb = symI(g_offb);
    int* idxf = symI(g_idxf);  int* idxb = symI(g_idxb);

    __half* hWs = hW;           __half* hWd = hW + NF;
    __half* hse = hW + 2*NF;    __half* hWf_ = hW + 3*NF;
    __half* hWb_ = hW + 4*NF;

    float* cse = cols;         float* cqe = cols + FF;
    float* sce = cols + 2*FF;  float* she = cols + 3*FF;
    float* csh = cols + 4*FF;  float* cqh = cols + 5*FF;
    float* sch = cols + 6*FF;  float* shh = cols + 7*FF;

    float* outH; float* outE;
    if (out_size >= NF + EF)      { outH = (float*)d_out; outE = (float*)d_out + NF; }
    else if (out_size == EF)      { outE = (float*)d_out; outH = htmp; }
    else                          { outH = (float*)d_out; outE = symF(g_dumpE); }

    cudaFuncSetAttribute(node_mma_k, cudaFuncAttributeMaxDynamicSharedMemorySize, SMEMB);
    cudaFuncSetAttribute(edge_mma_k, cudaFuncAttributeMaxDynamicSharedMemorySize, SMEMB);

    // weights (once)
    W6 w6; w6.p[0] = We; w6.p[1] = Ws; w6.p[2] = Wd; w6.p[3] = Wse; w6.p[4] = Wf; w6.p[5] = Wb;
    prep_w_k<<<(LL*6*WSZ)/256, 256>>>(w6, Wt);

    // inputs -> hi/lo (once)
    cvt_k<<<(NF/4 + 255)/256, 256>>>((const float4*)h0, (__half2*)hhi, (__half2*)hlo, NF/4);
    cvt_k<<<(EF/4 + 255)/256, 256>>>((const float4*)e0, (__half2*)ehi, (__half2*)elo, EF/4);

    // CSR (once per launch)
    zero_deg_k<<<(NN+255)/256, 256>>>(degf, degb);
    hist_k<<<(EE+255)/256, 256>>>(src, dst, degf, degb);
    scan_k<<<1, 1024>>>(degf, degb, offf, offb);
    curcpy_k<<<(NN+255)/256, 256>>>(offf, offb, degf, degb);
    fill_k<<<(EE+255)/256, 256>>>(src, dst, degf, degb, idxf, idxb);

    for (int l = 0; l < LL; l++) {
        __half* WtL = Wt + (size_t)l * 6 * WSZ;
        int last = (l == LL-1);

        init_k<<<(NN + 255)/256, 256>>>(mf, mb, denf, denb, cols);

        // node GEMMs: h @ {Ws, Wd, Wself, Wf, Wb}  (2-term hi/lo, fp16 out)
        O5 p; p.O[0] = hWs; p.O[1] = hWd; p.O[2] = hse; p.O[3] = hWf_; p.O[4] = hWb_;
        node_mma_k<<<dim3((NN + BM - 1)/BM, 1, 5), 512, SMEMB>>>(hhi, hlo, WtL, p, NN);

        // edge GEMM (1-term) + fused gather/logits/max/BN-stats, fp16 etmp out
        edge_mma_k<<<EE/BM, 512, SMEMB>>>(ehi, WtL, etmp, src, dst, hWs, hWd,
                                          attf + l*FF, attb + l*FF,
                                          logf, logb, mf, mb, cse, cqe);

        finalize_bn_k<<<1, 256>>>(cse, cqe, ge + l*FF, be + l*FF, 1.0f/EE, sce, she);
        exp_k<<<(EE + 255)/256, 256>>>(logf, logb, src, dst, mf, mb, exf, exb, denf, denb);

        // e residual (in-place hi/lo, fp16 etmp in, fp32 out on last layer)
        residual_k<true><<<(EF/4 + 255)/256, 256>>>((__half2*)ehi, (__half2*)elo,
                                                    etmp, sce, she,
                                                    (float4*)outE, EF/4, last);

        // attention aggregation (CSR gather, fp16 inputs) + node update + BN stats
        gather_node_k<<<(NN + 31)/32, 256>>>(offf, idxf, offb, idxb, src, dst,
                                             exf, denf, exb, denb,
                                             (const __half2*)hWf_, (const __half2*)hWb_,
                                             (const __half2*)hse, (float4*)htmp, csh, cqh);
        finalize_bn_k<<<1, 256>>>(csh, cqh, gh + l*FF, bh + l*FF, 1.0f/NN, sch, shh);

        // h residual (in-place hi/lo, fp32 htmp in, fp32 out on last layer)
        residual_k<false><<<(NF/4 + 255)/256, 256>>>((__half2*)hhi, (__half2*)hlo,
                                                     htmp, sch, shh,
                                                     (float4*)outH, NF/4, last);
    }
}

// round 12
// speedup vs baseline: 1.3603x; 1.3603x over previous
#include <cuda_runtime.h>
#include <cuda_fp16.h>
#include <math.h>
#include <stdint.h>

#define NN 50000
#define EE 800000
#define FF 256
#define NF (NN*FF)            // 12,800,000
#define EF (EE*FF)            // 204,800,000
#define LL 4
#define WK 256                // weight: single fp16 [N=256, K=256] K-major
#define WSZ (256*WK)

// GEMM tiling: BM=128, BN=256, BK=64, 512 threads (16 warps, 4x4)
#define BM 128
#define AST 72
#define BST 72
#define ABYTES (BM*AST*2)      // 18432
#define BBYTES (256*BST*2)     // 36864
#define BUFB (ABYTES + BBYTES) // 55296
#define SMEMB (2*BUFB)         // 110592

// ------------------------- scratch (device globals, no allocs) -------------
__device__ __half g_etmp[EF];      // fp16 e_tmp (streaming only)
__device__ float g_hW[5*NF];       // fp32: hWs | hWd | hself | hWf | hWb
__device__ float g_htmp[NF];
__device__ float g_logf[EE];
__device__ float g_logb[EE];
__device__ float g_exf[EE];
__device__ float g_exb[EE];
__device__ float g_mf[NN];
__device__ float g_mb[NN];
__device__ float g_denf[NN];
__device__ float g_denb[NN];
__device__ float g_cols[8*FF];
__device__ __half g_hhi[NF];
__device__ __half g_hlo[NF];
__device__ __half g_ehi[EF];       // e carried fp16 (hi only)
__device__ __half g_Wt[LL*6*WSZ];
__device__ float g_dumpE[EF];      // fallback-only fp32 sink
// CSR
__device__ int g_degf[NN];
__device__ int g_degb[NN];
__device__ int g_offf[NN+1];
__device__ int g_offb[NN+1];
__device__ int g_idxf[EE];
__device__ int g_idxb[EE];

// ------------------------- helpers -----------------------------------------
__device__ __forceinline__ uint32_t s2u(const void* p) {
    uint32_t a;
    asm("{ .reg .u64 t; cvta.to.shared.u64 t, %1; cvt.u32.u64 %0, t; }" : "=r"(a) : "l"(p));
    return a;
}
__device__ __forceinline__ void cp_async16(uint32_t saddr, const void* g) {
    asm volatile("cp.async.cg.shared.global [%0], [%1], 16;" :: "r"(saddr), "l"(g));
}
__device__ __forceinline__ void ldsm4(uint32_t addr, uint32_t& r0, uint32_t& r1,
                                      uint32_t& r2, uint32_t& r3) {
    asm volatile("ldmatrix.sync.aligned.m8n8.x4.shared.b16 {%0,%1,%2,%3}, [%4];"
                 : "=r"(r0), "=r"(r1), "=r"(r2), "=r"(r3) : "r"(addr));
}
__device__ __forceinline__ void mma16816(float* d, const uint32_t* a, const uint32_t* b) {
    asm volatile(
        "mma.sync.aligned.m16n8k16.row.col.f32.f16.f16.f32 "
        "{%0,%1,%2,%3}, {%4,%5,%6,%7}, {%8,%9}, {%0,%1,%2,%3};"
        : "+f"(d[0]), "+f"(d[1]), "+f"(d[2]), "+f"(d[3])
        : "r"(a[0]), "r"(a[1]), "r"(a[2]), "r"(a[3]), "r"(b[0]), "r"(b[1]));
}
__device__ __forceinline__ void atomicMaxF(float* a, float v) {
    int* ai = (int*)a;
    int old = __float_as_int(*a);
    while (__int_as_float(old) < v) {
        int prev = atomicCAS(ai, old, __float_as_int(v));
        if (prev == old) break;
        old = prev;
    }
}

// ------------------------- fp16 mma GEMM ------------------------------------
// TERMS=2: hi/lo split over 8 chunks; TERMS=1: hi only, 4 chunks.
// EDGE: adds gs[src]+gd[dst] (fp32) in epilogue, computes attention logits
// (+segment max) and BN column stats in fp32 (fused); stores C as fp16.
// Node: stores C as fp32.
template<bool EDGE, int TERMS>
__device__ __forceinline__ void mma_gemm(
    const __half* __restrict__ Ahi, const __half* __restrict__ Alo,
    const __half* __restrict__ Bt, void* __restrict__ C, int M, int tile,
    const int* __restrict__ src, const int* __restrict__ dst,
    const float* __restrict__ gs, const float* __restrict__ gd,
    const float* __restrict__ af, const float* __restrict__ ab,
    float* __restrict__ logf, float* __restrict__ logb,
    float* __restrict__ mf, float* __restrict__ mb,
    float* __restrict__ cse, float* __restrict__ cqe)
{
    extern __shared__ __align__(16) char smem[];
    const uint32_t sb = s2u(smem);
    const int tid = threadIdx.x, wid = tid >> 5, lane = tid & 31;
    const int m0 = tile * BM;
    const int NC = 4 * TERMS;

    auto load_chunk = [&](int c, int buf) {
        int g = (TERMS == 2) ? (c >> 1) : c;
        int t = (TERMS == 2) ? (c & 1) : 0;
        const __half* As = t ? Alo : Ahi;
        const int acol = g << 6;
        const int kb = g << 6;
        const uint32_t a_s = sb + buf*BUFB;
        const uint32_t b_s = a_s + ABYTES;
        #pragma unroll
        for (int i = 0; i < 2; i++) {            // A: 128x64 halves
            int v = tid + (i << 9); int r = v >> 3, c16 = v & 7;
            uint32_t sa = a_s + (r*AST + (c16 << 3))*2;
            int gr = m0 + r;
            if (EDGE) {
                cp_async16(sa, As + (size_t)gr*256 + acol + (c16 << 3));
            } else {
                if (gr < M) cp_async16(sa, As + (size_t)gr*256 + acol + (c16 << 3));
                else asm volatile("st.shared.v4.b32 [%0], {%1,%1,%1,%1};" :: "r"(sa), "r"(0));
            }
        }
        #pragma unroll
        for (int i = 0; i < 4; i++) {            // B: 256x64 halves
            int v = tid + (i << 9); int r = v >> 3, c16 = v & 7;
            cp_async16(b_s + (r*BST + (c16 << 3))*2, Bt + r*WK + kb + (c16 << 3));
        }
        asm volatile("cp.async.commit_group;");
    };

    const int wm = (wid & 3) << 5;               // 0..96
    const int wn = (wid >> 2) << 6;              // 0,64,128,192
    uint32_t a_off[2];
    #pragma unroll
    for (int im = 0; im < 2; im++)
        a_off[im] = ((wm + im*16 + (lane & 15))*AST + ((lane >> 4) << 3))*2;
    const uint32_t b_off = ((wn + ((lane >> 4) << 3) + (lane & 7))*BST
                           + (((lane >> 3) & 1) << 3))*2;

    float acc[2][8][4];
    #pragma unroll
    for (int im = 0; im < 2; im++)
        #pragma unroll
        for (int j = 0; j < 8; j++)
            #pragma unroll
            for (int q = 0; q < 4; q++) acc[im][j][q] = 0.f;

    load_chunk(0, 0);
    int buf = 0;
    for (int c = 0; c < NC; c++) {
        if (c < NC-1) {
            load_chunk(c + 1, buf ^ 1);
            asm volatile("cp.async.wait_group 1;");
        } else {
            asm volatile("cp.async.wait_group 0;");
        }
        __syncthreads();
        const uint32_t a_s = sb + buf*BUFB;
        const uint32_t b_s = a_s + ABYTES;
        #pragma unroll
        for (int ks = 0; ks < 4; ks++) {
            const uint32_t kh2 = (ks << 4)*2;
            uint32_t a[2][4], b[8][2];
            ldsm4(a_s + a_off[0] + kh2, a[0][0], a[0][1], a[0][2], a[0][3]);
            ldsm4(a_s + a_off[1] + kh2, a[1][0], a[1][1], a[1][2], a[1][3]);
            #pragma unroll
            for (int jp = 0; jp < 4; jp++)
                ldsm4(b_s + b_off + jp*(16*BST*2) + kh2,
                      b[2*jp][0], b[2*jp][1], b[2*jp+1][0], b[2*jp+1][1]);
            #pragma unroll
            for (int im = 0; im < 2; im++)
                #pragma unroll
                for (int j = 0; j < 8; j++)
                    mma16816(acc[im][j], a[im], b[j]);
        }
        __syncthreads();
        buf ^= 1;
    }

    // ---------------- epilogue ----------------
    const int gr0 = lane >> 2;
    const int cl0 = (lane & 3) << 1;

    if (!EDGE) {
        float* Cf = (float*)C;
        #pragma unroll
        for (int im = 0; im < 2; im++)
            #pragma unroll
            for (int half = 0; half < 2; half++) {
                int gm = m0 + wm + im*16 + gr0 + half*8;
                if (gm >= M) continue;
                #pragma unroll
                for (int j = 0; j < 8; j++) {
                    int col = wn + (j << 3) + cl0;
                    *(float2*)(Cf + (size_t)gm*256 + col) =
                        make_float2(acc[im][j][half*2], acc[im][j][half*2+1]);
                }
            }
        return;
    }

    // EDGE: fused gather + logits + BN stats, fp16 C store
    __half* Ch = (__half*)C;
    float* sred = (float*)smem;   // [0:128) rowf | [128:256) rowb | [256:512) cs | [512:768) cq
    for (int i = tid; i < 768; i += 512) sred[i] = 0.f;
    __syncthreads();

    float cs[16], cq[16];
    #pragma unroll
    for (int q = 0; q < 16; q++) { cs[q] = 0.f; cq[q] = 0.f; }

    #pragma unroll
    for (int im = 0; im < 2; im++)
        #pragma unroll
        for (int half = 0; half < 2; half++) {
            int rloc = wm + im*16 + gr0 + half*8;
            int gm = m0 + rloc;
            int s = src[gm], d = dst[gm];
            float pf = 0.f, pb = 0.f;
            #pragma unroll
            for (int j = 0; j < 8; j++) {
                int col = wn + (j << 3) + cl0;
                float2 o = make_float2(acc[im][j][half*2], acc[im][j][half*2+1]);
                float2 x = *(const float2*)(gs + (size_t)s*256 + col);
                float2 y = *(const float2*)(gd + (size_t)d*256 + col);
                o.x += x.x + y.x; o.y += x.y + y.y;
                *(__half2*)(Ch + (size_t)gm*256 + col) = __float22half2_rn(o);
                pf += o.x*__ldg(af+col) + o.y*__ldg(af+col+1);
                pb += o.x*__ldg(ab+col) + o.y*__ldg(ab+col+1);
                cs[j*2]   += o.x; cs[j*2+1] += o.y;
                cq[j*2]   += o.x*o.x; cq[j*2+1] += o.y*o.y;
            }
            pf += __shfl_xor_sync(0xFFFFFFFFu, pf, 1);
            pf += __shfl_xor_sync(0xFFFFFFFFu, pf, 2);
            pb += __shfl_xor_sync(0xFFFFFFFFu, pb, 1);
            pb += __shfl_xor_sync(0xFFFFFFFFu, pb, 2);
            if ((lane & 3) == 0) {
                atomicAdd(&sred[rloc], pf);
                atomicAdd(&sred[128 + rloc], pb);
            }
        }
    #pragma unroll
    for (int q = 0; q < 16; q++) {
        cs[q] += __shfl_xor_sync(0xFFFFFFFFu, cs[q], 4);
        cs[q] += __shfl_xor_sync(0xFFFFFFFFu, cs[q], 8);
        cs[q] += __shfl_xor_sync(0xFFFFFFFFu, cs[q], 16);
        cq[q] += __shfl_xor_sync(0xFFFFFFFFu, cq[q], 4);
        cq[q] += __shfl_xor_sync(0xFFFFFFFFu, cq[q], 8);
        cq[q] += __shfl_xor_sync(0xFFFFFFFFu, cq[q], 16);
    }
    if (lane < 4) {
        #pragma unroll
        for (int j = 0; j < 8; j++) {
            int col = wn + (j << 3) + ((lane & 3) << 1);
            atomicAdd(&sred[256 + col],     cs[j*2]);
            atomicAdd(&sred[256 + col + 1], cs[j*2+1]);
            atomicAdd(&sred[512 + col],     cq[j*2]);
            atomicAdd(&sred[512 + col + 1], cq[j*2+1]);
        }
    }
    __syncthreads();
    if (tid < 128) {
        int gm = m0 + tid;
        float lf = sred[tid];       lf = lf > 0.f ? lf : 0.2f*lf;
        float lb = sred[128 + tid]; lb = lb > 0.f ? lb : 0.2f*lb;
        logf[gm] = lf; logb[gm] = lb;
        atomicMaxF(&mf[dst[gm]], lf);
        atomicMaxF(&mb[src[gm]], lb);
    } else if (tid < 384) {
        int col = tid - 128;
        atomicAdd(&cse[col], sred[256 + col]);
        atomicAdd(&cqe[col], sred[512 + col]);
    }
}

struct O5 { float* O[5]; };

__global__ __launch_bounds__(512)
void node_mma_k(const __half* __restrict__ Ahi, const __half* __restrict__ Alo,
                const __half* __restrict__ WtL, O5 p, int M) {
    mma_gemm<false, 2>(Ahi, Alo, WtL + (size_t)(blockIdx.z + 1)*WSZ, p.O[blockIdx.z],
                       M, blockIdx.x, nullptr, nullptr, nullptr, nullptr,
                       nullptr, nullptr, nullptr, nullptr, nullptr, nullptr, nullptr, nullptr);
}

__global__ __launch_bounds__(512)
void edge_mma_k(const __half* __restrict__ Ahi,
                const __half* __restrict__ WtL, __half* __restrict__ C,
                const int* __restrict__ src, const int* __restrict__ dst,
                const float* __restrict__ gs, const float* __restrict__ gd,
                const float* __restrict__ af, const float* __restrict__ ab,
                float* __restrict__ logf, float* __restrict__ logb,
                float* __restrict__ mf, float* __restrict__ mb,
                float* __restrict__ cse, float* __restrict__ cqe) {
    mma_gemm<true, 1>(Ahi, Ahi, WtL, C, EE, blockIdx.x, src, dst, gs, gd,
                      af, ab, logf, logb, mf, mb, cse, cqe);
}

// ------------------------- prep / CSR ---------------------------------------
struct W6 { const float* p[6]; };

// Wt[l][w][n][k] fp16, K-major
__global__ void prep_w_k(W6 w, __half* __restrict__ out) {
    long idx = (long)blockIdx.x * 256 + threadIdx.x;      // LL*6*256*256
    int k = (int)(idx % WK); long t = idx / WK;
    int n = (int)(t % 256);  t /= 256;
    int wi = (int)(t % 6);   int l = (int)(t / 6);
    out[idx] = __float2half(w.p[wi][((size_t)l * 256 + k) * 256 + n]);
}

__global__ void cvt_k(const float4* __restrict__ x, __half2* __restrict__ hi,
                      __half2* __restrict__ lo, int n4) {
    int i = blockIdx.x * blockDim.x + threadIdx.x;
    if (i >= n4) return;
    float4 v = x[i];
    __half h0 = __float2half(v.x), h1 = __float2half(v.y);
    __half h2 = __float2half(v.z), h3 = __float2half(v.w);
    hi[2*i]   = __halves2half2(h0, h1);
    hi[2*i+1] = __halves2half2(h2, h3);
    lo[2*i]   = __halves2half2(__float2half(v.x - __half2float(h0)),
                               __float2half(v.y - __half2float(h1)));
    lo[2*i+1] = __halves2half2(__float2half(v.z - __half2float(h2)),
                               __float2half(v.w - __half2float(h3)));
}

__global__ void cvt_e_k(const float4* __restrict__ x, __half2* __restrict__ hi, int n4) {
    int i = blockIdx.x * blockDim.x + threadIdx.x;
    if (i >= n4) return;
    float4 v = x[i];
    hi[2*i]   = __float22half2_rn(make_float2(v.x, v.y));
    hi[2*i+1] = __float22half2_rn(make_float2(v.z, v.w));
}

__global__ void zero_deg_k(int* df, int* db) {
    int i = blockIdx.x*blockDim.x + threadIdx.x;
    if (i < NN) { df[i] = 0; db[i] = 0; }
}
__global__ void hist_k(const int* __restrict__ src, const int* __restrict__ dst,
                       int* df, int* db) {
    int e = blockIdx.x*blockDim.x + threadIdx.x;
    if (e >= EE) return;
    atomicAdd(&df[dst[e]], 1);
    atomicAdd(&db[src[e]], 1);
}
__global__ void scan_k(const int* __restrict__ degf, const int* __restrict__ degb,
                       int* offf, int* offb) {
    __shared__ int s[1024];
    for (int arr = 0; arr < 2; arr++) {
        const int* deg = arr ? degb : degf;
        int* off = arr ? offb : offf;
        int carry = 0;
        if (threadIdx.x == 0) off[0] = 0;
        for (int base = 0; base < NN; base += 1024) {
            int i = base + threadIdx.x;
            s[threadIdx.x] = (i < NN) ? deg[i] : 0;
            __syncthreads();
            for (int d = 1; d < 1024; d <<= 1) {
                int t = (threadIdx.x >= d) ? s[threadIdx.x - d] : 0;
                __syncthreads();
                s[threadIdx.x] += t;
                __syncthreads();
            }
            if (i < NN) off[i+1] = carry + s[threadIdx.x];
            carry += s[1023];
            __syncthreads();
        }
    }
}
__global__ void curcpy_k(const int* offf, const int* offb, int* curf, int* curb) {
    int i = blockIdx.x*blockDim.x + threadIdx.x;
    if (i < NN) { curf[i] = offf[i]; curb[i] = offb[i]; }
}
__global__ void fill_k(const int* __restrict__ src, const int* __restrict__ dst,
                       int* curf, int* curb, int* idxf, int* idxb) {
    int e = blockIdx.x*blockDim.x + threadIdx.x;
    if (e >= EE) return;
    idxf[atomicAdd(&curf[dst[e]], 1)] = e;
    idxb[atomicAdd(&curb[src[e]], 1)] = e;
}

// ------------------------- per-layer small kernels --------------------------
__global__ void init_k(float* mf, float* mb, float* denf, float* denb, float* cols) {
    int i = blockIdx.x*blockDim.x + threadIdx.x;
    if (i < NN) { mf[i] = -INFINITY; mb[i] = -INFINITY; denf[i] = 0.f; denb[i] = 0.f; }
    if (i < 8*FF) cols[i] = 0.f;
}

__global__ void finalize_bn_k(const float* __restrict__ colsum, const float* __restrict__ colsumsq,
                              const float* __restrict__ g, const float* __restrict__ b,
                              float invM, float* __restrict__ scale, float* __restrict__ shift) {
    int f = threadIdx.x;
    float mean = colsum[f] * invM;
    float var  = colsumsq[f] * invM - mean*mean;
    float sc   = g[f] * rsqrtf(var + 1e-5f);
    scale[f] = sc;
    shift[f] = b[f] - mean * sc;
}

__global__ void exp_k(const float* __restrict__ logf, const float* __restrict__ logb,
                      const int* __restrict__ src, const int* __restrict__ dst,
                      const float* __restrict__ mf, const float* __restrict__ mb,
                      float* __restrict__ exf, float* __restrict__ exb,
                      float* __restrict__ denf, float* __restrict__ denb) {
    int i = blockIdx.x*blockDim.x + threadIdx.x;
    if (i >= EE) return;
    int d = dst[i], s = src[i];
    float ef = expf(logf[i] - mf[d]);
    float eb = expf(logb[i] - mb[s]);
    exf[i] = ef; exb[i] = eb;
    atomicAdd(&denf[d], ef);
    atomicAdd(&denb[s], eb);
}

// e residual: ehi = fp16(ehi + relu(etmp*scale+shift)); etmp fp16; fp32 out on last
__global__ void residual_e_k(__half2* hi, const __half2* __restrict__ x,
                             const float* __restrict__ scale, const float* __restrict__ shift,
                             float4* __restrict__ outF, int n4, int writeF) {
    int i = blockIdx.x*blockDim.x + threadIdx.x;
    if (i >= n4) return;
    int c4 = i & 63;
    float2 a0 = __half22float2(hi[2*i]);
    float2 a1 = __half22float2(hi[2*i+1]);
    float2 x0 = __half22float2(x[2*i]);
    float2 x1 = __half22float2(x[2*i+1]);
    float4 sc = ((const float4*)scale)[c4];
    float4 sh = ((const float4*)shift)[c4];
    float4 r;
    r.x = a0.x + fmaxf(x0.x*sc.x + sh.x, 0.f);
    r.y = a0.y + fmaxf(x0.y*sc.y + sh.y, 0.f);
    r.z = a1.x + fmaxf(x1.x*sc.z + sh.z, 0.f);
    r.w = a1.y + fmaxf(x1.y*sc.w + sh.w, 0.f);
    hi[2*i]   = __float22half2_rn(make_float2(r.x, r.y));
    hi[2*i+1] = __float22half2_rn(make_float2(r.z, r.w));
    if (writeF) outF[i] = r;
}

// h residual: hi/lo carry, fp32 x (htmp); fp32 out on last
__global__ void residual_h_k(__half2* hi, __half2* lo, const float4* __restrict__ x,
                             const float* __restrict__ scale, const float* __restrict__ shift,
                             float4* __restrict__ outF, int n4, int writeF) {
    int i = blockIdx.x*blockDim.x + threadIdx.x;
    if (i >= n4) return;
    int c4 = i & 63;
    __half2 a0 = hi[2*i], a1 = hi[2*i+1], b0 = lo[2*i], b1 = lo[2*i+1];
    float4 base;
    base.x = __half2float(a0.x) + __half2float(b0.x);
    base.y = __half2float(a0.y) + __half2float(b0.y);
    base.z = __half2float(a1.x) + __half2float(b1.x);
    base.w = __half2float(a1.y) + __half2float(b1.y);
    float4 v  = x[i];
    float4 sc = ((const float4*)scale)[c4];
    float4 sh = ((const float4*)shift)[c4];
    float4 r;
    r.x = base.x + fmaxf(v.x*sc.x + sh.x, 0.f);
    r.y = base.y + fmaxf(v.y*sc.y + sh.y, 0.f);
    r.z = base.z + fmaxf(v.z*sc.z + sh.z, 0.f);
    r.w = base.w + fmaxf(v.w*sc.w + sh.w, 0.f);
    __half h0 = __float2half(r.x), h1 = __float2half(r.y);
    __half h2 = __float2half(r.z), h3 = __float2half(r.w);
    hi[2*i]   = __halves2half2(h0, h1);
    hi[2*i+1] = __halves2half2(h2, h3);
    lo[2*i]   = __halves2half2(__float2half(r.x - __half2float(h0)),
                               __float2half(r.y - __half2float(h1)));
    lo[2*i+1] = __halves2half2(__float2half(r.z - __half2float(h2)),
                               __float2half(r.w - __half2float(h3)));
    if (writeF) outF[i] = r;
}

// CSR gather aggregation + node update + BN stats (hW fp32, round-9 layout).
__global__ void gather_node_k(
    const int* __restrict__ offf, const int* __restrict__ idxf,
    const int* __restrict__ offb, const int* __restrict__ idxb,
    const int* __restrict__ src, const int* __restrict__ dst,
    const float* __restrict__ exf, const float* __restrict__ denf,
    const float* __restrict__ exb, const float* __restrict__ denb,
    const float4* __restrict__ hWf, const float4* __restrict__ hWb,
    const float4* __restrict__ hself, float4* __restrict__ htmp,
    float* __restrict__ colsum, float* __restrict__ colsumsq) {
    __shared__ float4 scs[256], scq[256];
    const int sub = threadIdx.x >> 6, c = threadIdx.x & 63;
    float4 csum = make_float4(0,0,0,0), csq = make_float4(0,0,0,0);
    #pragma unroll 1
    for (int nn = 0; nn < 8; nn++) {
        int node = blockIdx.x*32 + sub*8 + nn;
        if (node >= NN) break;
        float invf = 1.f/(denf[node] + 1e-9f);
        float invb = 1.f/(denb[node] + 1e-9f);
        float4 acc = hself[(size_t)node*64 + c];
        int e0 = offf[node], e1 = offf[node+1];
        for (int i = e0; i < e1; i++) {
            int e = idxf[i];
            float a = exf[e]*invf;
            float4 v = hWf[(size_t)src[e]*64 + c];
            acc.x += a*v.x; acc.y += a*v.y; acc.z += a*v.z; acc.w += a*v.w;
        }
        e0 = offb[node]; e1 = offb[node+1];
        for (int i = e0; i < e1; i++) {
            int e = idxb[i];
            float a = exb[e]*invb;
            float4 v = hWb[(size_t)dst[e]*64 + c];
            acc.x += a*v.x; acc.y += a*v.y; acc.z += a*v.z; acc.w += a*v.w;
        }
        htmp[(size_t)node*64 + c] = acc;
        csum.x += acc.x; csum.y += acc.y; csum.z += acc.z; csum.w += acc.w;
        csq.x += acc.x*acc.x; csq.y += acc.y*acc.y; csq.z += acc.z*acc.z; csq.w += acc.w*acc.w;
    }
    scs[threadIdx.x] = csum; scq[threadIdx.x] = csq;
    __syncthreads();
    if (sub == 0) {
        float4 s = scs[c], q = scq[c];
        #pragma unroll
        for (int k = 1; k < 4; k++) {
            float4 t = scs[k*64 + c], u = scq[k*64 + c];
            s.x += t.x; s.y += t.y; s.z += t.z; s.w += t.w;
            q.x += u.x; q.y += u.y; q.z += u.z; q.w += u.w;
        }
        atomicAdd(&colsum[c*4+0], s.x); atomicAdd(&colsum[c*4+1], s.y);
        atomicAdd(&colsum[c*4+2], s.z); atomicAdd(&colsum[c*4+3], s.w);
        atomicAdd(&colsumsq[c*4+0], q.x); atomicAdd(&colsumsq[c*4+1], q.y);
        atomicAdd(&colsumsq[c*4+2], q.z); atomicAdd(&colsumsq[c*4+3], q.w);
    }
}

// ------------------------- host orchestration ------------------------------
static float* symF(const void* s) { void* p = nullptr; cudaGetSymbolAddress(&p, s); return (float*)p; }
static int*   symI(const void* s) { void* p = nullptr; cudaGetSymbolAddress(&p, s); return (int*)p; }
static __half* symH(const void* s) { void* p = nullptr; cudaGetSymbolAddress(&p, s); return (__half*)p; }

extern "C" void kernel_launch(void* const* d_in, const int* in_sizes, int n_in,
                              void* d_out, int out_size) {
    const float* h0   = (const float*)d_in[0];
    const float* e0   = (const float*)d_in[1];
    const int*   src  = (const int*)d_in[2];
    const int*   dst  = (const int*)d_in[3];
    const float* We   = (const float*)d_in[4];
    const float* Ws   = (const float*)d_in[5];
    const float* Wd   = (const float*)d_in[6];
    const float* Wse  = (const float*)d_in[7];
    const float* Wf   = (const float*)d_in[8];
    const float* Wb   = (const float*)d_in[9];
    const float* attf = (const float*)d_in[10];
    const float* attb = (const float*)d_in[11];
    const float* ge   = (const float*)d_in[12];
    const float* be   = (const float*)d_in[13];
    const float* gh   = (const float*)d_in[14];
    const float* bh   = (const float*)d_in[15];

    __half* etmp = symH(g_etmp);
    float* hW   = symF(g_hW);
    float* htmp = symF(g_htmp);
    float* logf = symF(g_logf);
    float* logb = symF(g_logb);
    float* exf  = symF(g_exf);
    float* exb  = symF(g_exb);
    float* mf   = symF(g_mf);
    float* mb   = symF(g_mb);
    float* denf = symF(g_denf);
    float* denb = symF(g_denb);
    float* cols = symF(g_cols);
    __half* hhi = symH(g_hhi);
    __half* hlo = symH(g_hlo);
    __half* ehi = symH(g_ehi);
    __half* Wt  = symH(g_Wt);
    int* degf = symI(g_degf);  int* degb = symI(g_degb);
    int* offf = symI(g_offf);  int* offb = symI(g_offb);
    int* idxf = symI(g_idxf);  int* idxb = symI(g_idxb);

    float* hWs = hW;           float* hWd = hW + NF;
    float* hse = hW + 2*NF;    float* hWf_ = hW + 3*NF;
    float* hWb_ = hW + 4*NF;

    float* cse = cols;         float* cqe = cols + FF;
    float* sce = cols + 2*FF;  float* she = cols + 3*FF;
    float* csh = cols + 4*FF;  float* cqh = cols + 5*FF;
    float* sch = cols + 6*FF;  float* shh = cols + 7*FF;

    float* outH; float* outE;
    if (out_size >= NF + EF)      { outH = (float*)d_out; outE = (float*)d_out + NF; }
    else if (out_size == EF)      { outE = (float*)d_out; outH = htmp; }
    else                          { outH = (float*)d_out; outE = symF(g_dumpE); }

    cudaFuncSetAttribute(node_mma_k, cudaFuncAttributeMaxDynamicSharedMemorySize, SMEMB);
    cudaFuncSetAttribute(edge_mma_k, cudaFuncAttributeMaxDynamicSharedMemorySize, SMEMB);

    // weights (once)
    W6 w6; w6.p[0] = We; w6.p[1] = Ws; w6.p[2] = Wd; w6.p[3] = Wse; w6.p[4] = Wf; w6.p[5] = Wb;
    prep_w_k<<<(LL*6*WSZ)/256, 256>>>(w6, Wt);

    // inputs (once): h -> hi/lo; e -> hi only
    cvt_k<<<(NF/4 + 255)/256, 256>>>((const float4*)h0, (__half2*)hhi, (__half2*)hlo, NF/4);
    cvt_e_k<<<(EF/4 + 255)/256, 256>>>((const float4*)e0, (__half2*)ehi, EF/4);

    // CSR (once per launch)
    zero_deg_k<<<(NN+255)/256, 256>>>(degf, degb);
    hist_k<<<(EE+255)/256, 256>>>(src, dst, degf, degb);
    scan_k<<<1, 1024>>>(degf, degb, offf, offb);
    curcpy_k<<<(NN+255)/256, 256>>>(offf, offb, degf, degb);
    fill_k<<<(EE+255)/256, 256>>>(src, dst, degf, degb, idxf, idxb);

    for (int l = 0; l < LL; l++) {
        __half* WtL = Wt + (size_t)l * 6 * WSZ;
        int last = (l == LL-1);

        init_k<<<(NN + 255)/256, 256>>>(mf, mb, denf, denb, cols);

        // node GEMMs: h @ {Ws, Wd, Wself, Wf, Wb}  (2-term hi/lo, fp32 out)
        O5 p; p.O[0] = hWs; p.O[1] = hWd; p.O[2] = hse; p.O[3] = hWf_; p.O[4] = hWb_;
        node_mma_k<<<dim3((NN + BM - 1)/BM, 1, 5), 512, SMEMB>>>(hhi, hlo, WtL, p, NN);

        // edge GEMM (1-term, ehi) + fused gather/logits/max/BN-stats, fp16 etmp out
        edge_mma_k<<<EE/BM, 512, SMEMB>>>(ehi, WtL, etmp, src, dst, hWs, hWd,
                                          attf + l*FF, attb + l*FF,
                                          logf, logb, mf, mb, cse, cqe);

        finalize_bn_k<<<1, 256>>>(cse, cqe, ge + l*FF, be + l*FF, 1.0f/EE, sce, she);
        exp_k<<<(EE + 255)/256, 256>>>(logf, logb, src, dst, mf, mb, exf, exb, denf, denb);

        // e residual (fp16 in-place, fp32 out on last layer)
        residual_e_k<<<(EF/4 + 255)/256, 256>>>((__half2*)ehi, (const __half2*)etmp,
                                                sce, she, (float4*)outE, EF/4, last);

        // attention aggregation (CSR gather, fp32) + node update + BN stats
        gather_node_k<<<(NN + 31)/32, 256>>>(offf, idxf, offb, idxb, src, dst,
                                             exf, denf, exb, denb,
                                             (const float4*)hWf_, (const float4*)hWb_,
                                             (const float4*)hse, (float4*)htmp, csh, cqh);
        finalize_bn_k<<<1, 256>>>(csh, cqh, gh + l*FF, bh + l*FF, 1.0f/NN, sch, shh);

        // h residual (hi/lo, fp32 out on last layer)
        residual_h_k<<<(NF/4 + 255)/256, 256>>>((__half2*)hhi, (__half2*)hlo,
                                                (const float4*)htmp, sch, shh,
                                                (float4*)outH, NF/4, last);
    }
}

// round 14
// speedup vs baseline: 1.4238x; 1.0467x over previous
#include <cuda_runtime.h>
#include <cuda_fp16.h>
#include <math.h>
#include <stdint.h>

#define NN 50000
#define EE 800000
#define FF 256
#define NF (NN*FF)            // 12,800,000
#define EF (EE*FF)            // 204,800,000
#define LL 4
#define WK 256                // weight: single fp16 [N=256, K=256] K-major
#define WSZ (256*WK)

// GEMM tiling: BM=128, BN=256, BK=64, 512 threads (16 warps, 4x4)
#define BM 128
#define AST 72
#define BST 72
#define ABYTES (BM*AST*2)      // 18432
#define BBYTES (256*BST*2)     // 36864
#define BUFB (ABYTES + BBYTES) // 55296
#define SMEMB (2*BUFB)         // 110592

// ------------------------- scratch (device globals, no allocs) -------------
__device__ __half g_etmp[EF];      // fp16 e_tmp (streaming only)
__device__ float g_hW[5*NF];       // fp32: hWs | hWd | hself | hWf | hWb
__device__ float g_htmp[NF];
__device__ float g_logf[EE];
__device__ float g_logb[EE];
__device__ float g_exf[EE];
__device__ float g_exb[EE];
__device__ float g_mf[NN];
__device__ float g_mb[NN];
__device__ float g_denf[NN];
__device__ float g_denb[NN];
__device__ float g_cols[8*FF];
__device__ __half g_hhi[NF];
__device__ __half g_hlo[NF];
__device__ __half g_ehi[EF];       // e carried fp16 (hi only)
__device__ __half g_Wt[LL*6*WSZ];
__device__ float g_dumpE[EF];      // fallback-only fp32 sink
// CSR
__device__ int g_degf[NN];
__device__ int g_degb[NN];
__device__ int g_offf[NN+1];
__device__ int g_offb[NN+1];
__device__ int g_idxf[EE];
__device__ int g_idxb[EE];

// ------------------------- helpers -----------------------------------------
__device__ __forceinline__ uint32_t s2u(const void* p) {
    uint32_t a;
    asm("{ .reg .u64 t; cvta.to.shared.u64 t, %1; cvt.u32.u64 %0, t; }" : "=r"(a) : "l"(p));
    return a;
}
__device__ __forceinline__ void cp_async16(uint32_t saddr, const void* g) {
    asm volatile("cp.async.cg.shared.global [%0], [%1], 16;" :: "r"(saddr), "l"(g));
}
__device__ __forceinline__ void ldsm4(uint32_t addr, uint32_t& r0, uint32_t& r1,
                                      uint32_t& r2, uint32_t& r3) {
    asm volatile("ldmatrix.sync.aligned.m8n8.x4.shared.b16 {%0,%1,%2,%3}, [%4];"
                 : "=r"(r0), "=r"(r1), "=r"(r2), "=r"(r3) : "r"(addr));
}
__device__ __forceinline__ void mma16816(float* d, const uint32_t* a, const uint32_t* b) {
    asm volatile(
        "mma.sync.aligned.m16n8k16.row.col.f32.f16.f16.f32 "
        "{%0,%1,%2,%3}, {%4,%5,%6,%7}, {%8,%9}, {%0,%1,%2,%3};"
        : "+f"(d[0]), "+f"(d[1]), "+f"(d[2]), "+f"(d[3])
        : "r"(a[0]), "r"(a[1]), "r"(a[2]), "r"(a[3]), "r"(b[0]), "r"(b[1]));
}
__device__ __forceinline__ void atomicMaxF(float* a, float v) {
    int* ai = (int*)a;
    int old = __float_as_int(*a);
    while (__int_as_float(old) < v) {
        int prev = atomicCAS(ai, old, __float_as_int(v));
        if (prev == old) break;
        old = prev;
    }
}

// ------------------------- fp16 mma GEMM ------------------------------------
// TERMS=2: hi/lo split over 8 chunks; TERMS=1: hi only, 4 chunks.
// EDGE: adds gs[src]+gd[dst] (fp32) in epilogue, computes attention logits
// (+segment max) and BN column stats in fp32 (fused); stores C as fp16.
// Node: stores C as fp32.
template<bool EDGE, int TERMS>
__device__ __forceinline__ void mma_gemm(
    const __half* __restrict__ Ahi, const __half* __restrict__ Alo,
    const __half* __restrict__ Bt, void* __restrict__ C, int M, int tile,
    const int* __restrict__ src, const int* __restrict__ dst,
    const float* __restrict__ gs, const float* __restrict__ gd,
    const float* __restrict__ af, const float* __restrict__ ab,
    float* __restrict__ logf, float* __restrict__ logb,
    float* __restrict__ mf, float* __restrict__ mb,
    float* __restrict__ cse, float* __restrict__ cqe)
{
    extern __shared__ __align__(16) char smem[];
    const uint32_t sb = s2u(smem);
    const int tid = threadIdx.x, wid = tid >> 5, lane = tid & 31;
    const int m0 = tile * BM;
    const int NC = 4 * TERMS;

    auto load_chunk = [&](int c, int buf) {
        int g = (TERMS == 2) ? (c >> 1) : c;
        int t = (TERMS == 2) ? (c & 1) : 0;
        const __half* As = t ? Alo : Ahi;
        const int acol = g << 6;
        const int kb = g << 6;
        const uint32_t a_s = sb + buf*BUFB;
        const uint32_t b_s = a_s + ABYTES;
        #pragma unroll
        for (int i = 0; i < 2; i++) {            // A: 128x64 halves
            int v = tid + (i << 9); int r = v >> 3, c16 = v & 7;
            uint32_t sa = a_s + (r*AST + (c16 << 3))*2;
            int gr = m0 + r;
            if (EDGE) {
                cp_async16(sa, As + (size_t)gr*256 + acol + (c16 << 3));
            } else {
                if (gr < M) cp_async16(sa, As + (size_t)gr*256 + acol + (c16 << 3));
                else asm volatile("st.shared.v4.b32 [%0], {%1,%1,%1,%1};" :: "r"(sa), "r"(0));
            }
        }
        #pragma unroll
        for (int i = 0; i < 4; i++) {            // B: 256x64 halves
            int v = tid + (i << 9); int r = v >> 3, c16 = v & 7;
            cp_async16(b_s + (r*BST + (c16 << 3))*2, Bt + r*WK + kb + (c16 << 3));
        }
        asm volatile("cp.async.commit_group;");
    };

    const int wm = (wid & 3) << 5;               // 0..96
    const int wn = (wid >> 2) << 6;              // 0,64,128,192
    uint32_t a_off[2];
    #pragma unroll
    for (int im = 0; im < 2; im++)
        a_off[im] = ((wm + im*16 + (lane & 15))*AST + ((lane >> 4) << 3))*2;
    const uint32_t b_off = ((wn + ((lane >> 4) << 3) + (lane & 7))*BST
                           + (((lane >> 3) & 1) << 3))*2;

    float acc[2][8][4];
    #pragma unroll
    for (int im = 0; im < 2; im++)
        #pragma unroll
        for (int j = 0; j < 8; j++)
            #pragma unroll
            for (int q = 0; q < 4; q++) acc[im][j][q] = 0.f;

    load_chunk(0, 0);
    int buf = 0;
    for (int c = 0; c < NC; c++) {
        if (c < NC-1) {
            load_chunk(c + 1, buf ^ 1);
            asm volatile("cp.async.wait_group 1;");
        } else {
            asm volatile("cp.async.wait_group 0;");
        }
        __syncthreads();
        const uint32_t a_s = sb + buf*BUFB;
        const uint32_t b_s = a_s + ABYTES;
        #pragma unroll
        for (int ks = 0; ks < 4; ks++) {
            const uint32_t kh2 = (ks << 4)*2;
            uint32_t a[2][4], b[8][2];
            ldsm4(a_s + a_off[0] + kh2, a[0][0], a[0][1], a[0][2], a[0][3]);
            ldsm4(a_s + a_off[1] + kh2, a[1][0], a[1][1], a[1][2], a[1][3]);
            #pragma unroll
            for (int jp = 0; jp < 4; jp++)
                ldsm4(b_s + b_off + jp*(16*BST*2) + kh2,
                      b[2*jp][0], b[2*jp][1], b[2*jp+1][0], b[2*jp+1][1]);
            #pragma unroll
            for (int im = 0; im < 2; im++)
                #pragma unroll
                for (int j = 0; j < 8; j++)
                    mma16816(acc[im][j], a[im], b[j]);
        }
        __syncthreads();
        buf ^= 1;
    }

    // ---------------- epilogue ----------------
    const int gr0 = lane >> 2;
    const int cl0 = (lane & 3) << 1;

    if (!EDGE) {
        float* Cf = (float*)C;
        #pragma unroll
        for (int im = 0; im < 2; im++)
            #pragma unroll
            for (int half = 0; half < 2; half++) {
                int gm = m0 + wm + im*16 + gr0 + half*8;
                if (gm >= M) continue;
                #pragma unroll
                for (int j = 0; j < 8; j++) {
                    int col = wn + (j << 3) + cl0;
                    *(float2*)(Cf + (size_t)gm*256 + col) =
                        make_float2(acc[im][j][half*2], acc[im][j][half*2+1]);
                }
            }
        return;
    }

    // EDGE: fused gather + logits + BN stats, fp16 C store
    __half* Ch = (__half*)C;
    float* sred = (float*)smem;   // [0:128) rowf | [128:256) rowb | [256:512) cs | [512:768) cq
    for (int i = tid; i < 768; i += 512) sred[i] = 0.f;
    __syncthreads();

    float cs[16], cq[16];
    #pragma unroll
    for (int q = 0; q < 16; q++) { cs[q] = 0.f; cq[q] = 0.f; }

    #pragma unroll
    for (int im = 0; im < 2; im++)
        #pragma unroll
        for (int half = 0; half < 2; half++) {
            int rloc = wm + im*16 + gr0 + half*8;
            int gm = m0 + rloc;
            int s = src[gm], d = dst[gm];
            float pf = 0.f, pb = 0.f;
            #pragma unroll
            for (int j = 0; j < 8; j++) {
                int col = wn + (j << 3) + cl0;
                float2 o = make_float2(acc[im][j][half*2], acc[im][j][half*2+1]);
                float2 x = *(const float2*)(gs + (size_t)s*256 + col);
                float2 y = *(const float2*)(gd + (size_t)d*256 + col);
                o.x += x.x + y.x; o.y += x.y + y.y;
                *(__half2*)(Ch + (size_t)gm*256 + col) = __float22half2_rn(o);
                pf += o.x*__ldg(af+col) + o.y*__ldg(af+col+1);
                pb += o.x*__ldg(ab+col) + o.y*__ldg(ab+col+1);
                cs[j*2]   += o.x; cs[j*2+1] += o.y;
                cq[j*2]   += o.x*o.x; cq[j*2+1] += o.y*o.y;
            }
            pf += __shfl_xor_sync(0xFFFFFFFFu, pf, 1);
            pf += __shfl_xor_sync(0xFFFFFFFFu, pf, 2);
            pb += __shfl_xor_sync(0xFFFFFFFFu, pb, 1);
            pb += __shfl_xor_sync(0xFFFFFFFFu, pb, 2);
            if ((lane & 3) == 0) {
                atomicAdd(&sred[rloc], pf);
                atomicAdd(&sred[128 + rloc], pb);
            }
        }
    #pragma unroll
    for (int q = 0; q < 16; q++) {
        cs[q] += __shfl_xor_sync(0xFFFFFFFFu, cs[q], 4);
        cs[q] += __shfl_xor_sync(0xFFFFFFFFu, cs[q], 8);
        cs[q] += __shfl_xor_sync(0xFFFFFFFFu, cs[q], 16);
        cq[q] += __shfl_xor_sync(0xFFFFFFFFu, cq[q], 4);
        cq[q] += __shfl_xor_sync(0xFFFFFFFFu, cq[q], 8);
        cq[q] += __shfl_xor_sync(0xFFFFFFFFu, cq[q], 16);
    }
    if (lane < 4) {
        #pragma unroll
        for (int j = 0; j < 8; j++) {
            int col = wn + (j << 3) + ((lane & 3) << 1);
            atomicAdd(&sred[256 + col],     cs[j*2]);
            atomicAdd(&sred[256 + col + 1], cs[j*2+1]);
            atomicAdd(&sred[512 + col],     cq[j*2]);
            atomicAdd(&sred[512 + col + 1], cq[j*2+1]);
        }
    }
    __syncthreads();
    if (tid < 128) {
        int gm = m0 + tid;
        float lf = sred[tid];       lf = lf > 0.f ? lf : 0.2f*lf;
        float lb = sred[128 + tid]; lb = lb > 0.f ? lb : 0.2f*lb;
        logf[gm] = lf; logb[gm] = lb;
        atomicMaxF(&mf[dst[gm]], lf);
        atomicMaxF(&mb[src[gm]], lb);
    } else if (tid < 384) {
        int col = tid - 128;
        atomicAdd(&cse[col], sred[256 + col]);
        atomicAdd(&cqe[col], sred[512 + col]);
    }
}

struct O5 { float* O[5]; };

__global__ __launch_bounds__(512)
void node_mma_k(const __half* __restrict__ Ahi,
                const __half* __restrict__ WtL, O5 p, int M) {
    mma_gemm<false, 1>(Ahi, Ahi, WtL + (size_t)(blockIdx.z + 1)*WSZ, p.O[blockIdx.z],
                       M, blockIdx.x, nullptr, nullptr, nullptr, nullptr,
                       nullptr, nullptr, nullptr, nullptr, nullptr, nullptr, nullptr, nullptr);
}

__global__ __launch_bounds__(512)
void edge_mma_k(const __half* __restrict__ Ahi,
                const __half* __restrict__ WtL, __half* __restrict__ C,
                const int* __restrict__ src, const int* __restrict__ dst,
                const float* __restrict__ gs, const float* __restrict__ gd,
                const float* __restrict__ af, const float* __restrict__ ab,
                float* __restrict__ logf, float* __restrict__ logb,
                float* __restrict__ mf, float* __restrict__ mb,
                float* __restrict__ cse, float* __restrict__ cqe) {
    mma_gemm<true, 1>(Ahi, Ahi, WtL, C, EE, blockIdx.x, src, dst, gs, gd,
                      af, ab, logf, logb, mf, mb, cse, cqe);
}

// ------------------------- prep / CSR ---------------------------------------
struct W6 { const float* p[6]; };

// Wt[l][w][n][k] fp16, K-major
__global__ void prep_w_k(W6 w, __half* __restrict__ out) {
    long idx = (long)blockIdx.x * 256 + threadIdx.x;      // LL*6*256*256
    int k = (int)(idx % WK); long t = idx / WK;
    int n = (int)(t % 256);  t /= 256;
    int wi = (int)(t % 6);   int l = (int)(t / 6);
    out[idx] = __float2half(w.p[wi][((size_t)l * 256 + k) * 256 + n]);
}

__global__ void cvt_k(const float4* __restrict__ x, __half2* __restrict__ hi,
                      __half2* __restrict__ lo, int n4) {
    int i = blockIdx.x * blockDim.x + threadIdx.x;
    if (i >= n4) return;
    float4 v = x[i];
    __half h0 = __float2half(v.x), h1 = __float2half(v.y);
    __half h2 = __float2half(v.z), h3 = __float2half(v.w);
    hi[2*i]   = __halves2half2(h0, h1);
    hi[2*i+1] = __halves2half2(h2, h3);
    lo[2*i]   = __halves2half2(__float2half(v.x - __half2float(h0)),
                               __float2half(v.y - __half2float(h1)));
    lo[2*i+1] = __halves2half2(__float2half(v.z - __half2float(h2)),
                               __float2half(v.w - __half2float(h3)));
}

__global__ void cvt_e_k(const float4* __restrict__ x, __half2* __restrict__ hi, int n4) {
    int i = blockIdx.x * blockDim.x + threadIdx.x;
    if (i >= n4) return;
    float4 v = x[i];
    hi[2*i]   = __float22half2_rn(make_float2(v.x, v.y));
    hi[2*i+1] = __float22half2_rn(make_float2(v.z, v.w));
}

__global__ void zero_deg_k(int* df, int* db) {
    int i = blockIdx.x*blockDim.x + threadIdx.x;
    if (i < NN) { df[i] = 0; db[i] = 0; }
}
__global__ void hist_k(const int* __restrict__ src, const int* __restrict__ dst,
                       int* df, int* db) {
    int e = blockIdx.x*blockDim.x + threadIdx.x;
    if (e >= EE) return;
    atomicAdd(&df[dst[e]], 1);
    atomicAdd(&db[src[e]], 1);
}
__global__ void scan_k(const int* __restrict__ degf, const int* __restrict__ degb,
                       int* offf, int* offb) {
    __shared__ int s[1024];
    for (int arr = 0; arr < 2; arr++) {
        const int* deg = arr ? degb : degf;
        int* off = arr ? offb : offf;
        int carry = 0;
        if (threadIdx.x == 0) off[0] = 0;
        for (int base = 0; base < NN; base += 1024) {
            int i = base + threadIdx.x;
            s[threadIdx.x] = (i < NN) ? deg[i] : 0;
            __syncthreads();
            for (int d = 1; d < 1024; d <<= 1) {
                int t = (threadIdx.x >= d) ? s[threadIdx.x - d] : 0;
                __syncthreads();
                s[threadIdx.x] += t;
                __syncthreads();
            }
            if (i < NN) off[i+1] = carry + s[threadIdx.x];
            carry += s[1023];
            __syncthreads();
        }
    }
}
__global__ void curcpy_k(const int* offf, const int* offb, int* curf, int* curb) {
    int i = blockIdx.x*blockDim.x + threadIdx.x;
    if (i < NN) { curf[i] = offf[i]; curb[i] = offb[i]; }
}
__global__ void fill_k(const int* __restrict__ src, const int* __restrict__ dst,
                       int* curf, int* curb, int* idxf, int* idxb) {
    int e = blockIdx.x*blockDim.x + threadIdx.x;
    if (e >= EE) return;
    idxf[atomicAdd(&curf[dst[e]], 1)] = e;
    idxb[atomicAdd(&curb[src[e]], 1)] = e;
}

// ------------------------- per-layer small kernels --------------------------
__global__ void init_k(float* mf, float* mb, float* denf, float* denb, float* cols) {
    int i = blockIdx.x*blockDim.x + threadIdx.x;
    if (i < NN) { mf[i] = -INFINITY; mb[i] = -INFINITY; denf[i] = 0.f; denb[i] = 0.f; }
    if (i < 8*FF) cols[i] = 0.f;
}

__global__ void finalize_bn_k(const float* __restrict__ colsum, const float* __restrict__ colsumsq,
                              const float* __restrict__ g, const float* __restrict__ b,
                              float invM, float* __restrict__ scale, float* __restrict__ shift) {
    int f = threadIdx.x;
    float mean = colsum[f] * invM;
    float var  = colsumsq[f] * invM - mean*mean;
    float sc   = g[f] * rsqrtf(var + 1e-5f);
    scale[f] = sc;
    shift[f] = b[f] - mean * sc;
}

__global__ void exp_k(const float* __restrict__ logf, const float* __restrict__ logb,
                      const int* __restrict__ src, const int* __restrict__ dst,
                      const float* __restrict__ mf, const float* __restrict__ mb,
                      float* __restrict__ exf, float* __restrict__ exb,
                      float* __restrict__ denf, float* __restrict__ denb) {
    int i = blockIdx.x*blockDim.x + threadIdx.x;
    if (i >= EE) return;
    int d = dst[i], s = src[i];
    float ef = expf(logf[i] - mf[d]);
    float eb = expf(logb[i] - mb[s]);
    exf[i] = ef; exb[i] = eb;
    atomicAdd(&denf[d], ef);
    atomicAdd(&denb[s], eb);
}

// e residual: ehi = fp16(ehi + relu(etmp*scale+shift)); 16B-wide; fp32 out on last
__global__ void residual_e_k(uint4* __restrict__ hi, const uint4* __restrict__ x,
                             const float* __restrict__ scale, const float* __restrict__ shift,
                             float4* __restrict__ outF, int n8, int writeF) {
    int i = blockIdx.x*blockDim.x + threadIdx.x;
    if (i >= n8) return;
    int c8 = i & 31;                       // 8-element column group (256/8)
    uint4 hv = hi[i];
    uint4 xv = x[i];
    const __half2* hp = (const __half2*)&hv;
    const __half2* xp = (const __half2*)&xv;
    float4 sc0 = ((const float4*)scale)[c8*2],  sc1 = ((const float4*)scale)[c8*2+1];
    float4 sh0 = ((const float4*)shift)[c8*2],  sh1 = ((const float4*)shift)[c8*2+1];
    float r[8];
    {
        float2 a = __half22float2(hp[0]), b = __half22float2(xp[0]);
        r[0] = a.x + fmaxf(b.x*sc0.x + sh0.x, 0.f);
        r[1] = a.y + fmaxf(b.y*sc0.y + sh0.y, 0.f);
        a = __half22float2(hp[1]); b = __half22float2(xp[1]);
        r[2] = a.x + fmaxf(b.x*sc0.z + sh0.z, 0.f);
        r[3] = a.y + fmaxf(b.y*sc0.w + sh0.w, 0.f);
        a = __half22float2(hp[2]); b = __half22float2(xp[2]);
        r[4] = a.x + fmaxf(b.x*sc1.x + sh1.x, 0.f);
        r[5] = a.y + fmaxf(b.y*sc1.y + sh1.y, 0.f);
        a = __half22float2(hp[3]); b = __half22float2(xp[3]);
        r[6] = a.x + fmaxf(b.x*sc1.z + sh1.z, 0.f);
        r[7] = a.y + fmaxf(b.y*sc1.w + sh1.w, 0.f);
    }
    uint4 ov;
    __half2* op = (__half2*)&ov;
    op[0] = __float22half2_rn(make_float2(r[0], r[1]));
    op[1] = __float22half2_rn(make_float2(r[2], r[3]));
    op[2] = __float22half2_rn(make_float2(r[4], r[5]));
    op[3] = __float22half2_rn(make_float2(r[6], r[7]));
    hi[i] = ov;
    if (writeF) {
        outF[2*i]   = make_float4(r[0], r[1], r[2], r[3]);
        outF[2*i+1] = make_float4(r[4], r[5], r[6], r[7]);
    }
}

// h residual: hi/lo carry, fp32 x (htmp); fp32 out on last
__global__ void residual_h_k(__half2* hi, __half2* lo, const float4* __restrict__ x,
                             const float* __restrict__ scale, const float* __restrict__ shift,
                             float4* __restrict__ outF, int n4, int writeF) {
    int i = blockIdx.x*blockDim.x + threadIdx.x;
    if (i >= n4) return;
    int c4 = i & 63;
    __half2 a0 = hi[2*i], a1 = hi[2*i+1], b0 = lo[2*i], b1 = lo[2*i+1];
    float4 base;
    base.x = __half2float(a0.x) + __half2float(b0.x);
    base.y = __half2float(a0.y) + __half2float(b0.y);
    base.z = __half2float(a1.x) + __half2float(b1.x);
    base.w = __half2float(a1.y) + __half2float(b1.y);
    float4 v  = x[i];
    float4 sc = ((const float4*)scale)[c4];
    float4 sh = ((const float4*)shift)[c4];
    float4 r;
    r.x = base.x + fmaxf(v.x*sc.x + sh.x, 0.f);
    r.y = base.y + fmaxf(v.y*sc.y + sh.y, 0.f);
    r.z = base.z + fmaxf(v.z*sc.z + sh.z, 0.f);
    r.w = base.w + fmaxf(v.w*sc.w + sh.w, 0.f);
    __half h0 = __float2half(r.x), h1 = __float2half(r.y);
    __half h2 = __float2half(r.z), h3 = __float2half(r.w);
    hi[2*i]   = __halves2half2(h0, h1);
    hi[2*i+1] = __halves2half2(h2, h3);
    lo[2*i]   = __halves2half2(__float2half(r.x - __half2float(h0)),
                               __float2half(r.y - __half2float(h1)));
    lo[2*i+1] = __halves2half2(__float2half(r.z - __half2float(h2)),
                               __float2half(r.w - __half2float(h3)));
    if (writeF) outF[i] = r;
}

// CSR gather aggregation + node update + BN stats (hW fp32).
__global__ void gather_node_k(
    const int* __restrict__ offf, const int* __restrict__ idxf,
    const int* __restrict__ offb, const int* __restrict__ idxb,
    const int* __restrict__ src, const int* __restrict__ dst,
    const float* __restrict__ exf, const float* __restrict__ denf,
    const float* __restrict__ exb, const float* __restrict__ denb,
    const float4* __restrict__ hWf, const float4* __restrict__ hWb,
    const float4* __restrict__ hself, float4* __restrict__ htmp,
    float* __restrict__ colsum, float* __restrict__ colsumsq) {
    __shared__ float4 scs[256], scq[256];
    const int sub = threadIdx.x >> 6, c = threadIdx.x & 63;
    float4 csum = make_float4(0,0,0,0), csq = make_float4(0,0,0,0);
    #pragma unroll 1
    for (int nn = 0; nn < 8; nn++) {
        int node = blockIdx.x*32 + sub*8 + nn;
        if (node >= NN) break;
        float invf = 1.f/(denf[node] + 1e-9f);
        float invb = 1.f/(denb[node] + 1e-9f);
        float4 acc = hself[(size_t)node*64 + c];
        int e0 = offf[node], e1 = offf[node+1];
        for (int i = e0; i < e1; i++) {
            int e = idxf[i];
            float a = exf[e]*invf;
            float4 v = hWf[(size_t)src[e]*64 + c];
            acc.x += a*v.x; acc.y += a*v.y; acc.z += a*v.z; acc.w += a*v.w;
        }
        e0 = offb[node]; e1 = offb[node+1];
        for (int i = e0; i < e1; i++) {
            int e = idxb[i];
            float a = exb[e]*invb;
            float4 v = hWb[(size_t)dst[e]*64 + c];
            acc.x += a*v.x; acc.y += a*v.y; acc.z += a*v.z; acc.w += a*v.w;
        }
        htmp[(size_t)node*64 + c] = acc;
        csum.x += acc.x; csum.y += acc.y; csum.z += acc.z; csum.w += acc.w;
        csq.x += acc.x*acc.x; csq.y += acc.y*acc.y; csq.z += acc.z*acc.z; csq.w += acc.w*acc.w;
    }
    scs[threadIdx.x] = csum; scq[threadIdx.x] = csq;
    __syncthreads();
    if (sub == 0) {
        float4 s = scs[c], q = scq[c];
        #pragma unroll
        for (int k = 1; k < 4; k++) {
            float4 t = scs[k*64 + c], u = scq[k*64 + c];
            s.x += t.x; s.y += t.y; s.z += t.z; s.w += t.w;
            q.x += u.x; q.y += u.y; q.z += u.z; q.w += u.w;
        }
        atomicAdd(&colsum[c*4+0], s.x); atomicAdd(&colsum[c*4+1], s.y);
        atomicAdd(&colsum[c*4+2], s.z); atomicAdd(&colsum[c*4+3], s.w);
        atomicAdd(&colsumsq[c*4+0], q.x); atomicAdd(&colsumsq[c*4+1], q.y);
        atomicAdd(&colsumsq[c*4+2], q.z); atomicAdd(&colsumsq[c*4+3], q.w);
    }
}

// ------------------------- host orchestration ------------------------------
static float* symF(const void* s) { void* p = nullptr; cudaGetSymbolAddress(&p, s); return (float*)p; }
static int*   symI(const void* s) { void* p = nullptr; cudaGetSymbolAddress(&p, s); return (int*)p; }
static __half* symH(const void* s) { void* p = nullptr; cudaGetSymbolAddress(&p, s); return (__half*)p; }

extern "C" void kernel_launch(void* const* d_in, const int* in_sizes, int n_in,
                              void* d_out, int out_size) {
    const float* h0   = (const float*)d_in[0];
    const float* e0   = (const float*)d_in[1];
    const int*   src  = (const int*)d_in[2];
    const int*   dst  = (const int*)d_in[3];
    const float* We   = (const float*)d_in[4];
    const float* Ws   = (const float*)d_in[5];
    const float* Wd   = (const float*)d_in[6];
    const float* Wse  = (const float*)d_in[7];
    const float* Wf   = (const float*)d_in[8];
    const float* Wb   = (const float*)d_in[9];
    const float* attf = (const float*)d_in[10];
    const float* attb = (const float*)d_in[11];
    const float* ge   = (const float*)d_in[12];
    const float* be   = (const float*)d_in[13];
    const float* gh   = (const float*)d_in[14];
    const float* bh   = (const float*)d_in[15];

    __half* etmp = symH(g_etmp);
    float* hW   = symF(g_hW);
    float* htmp = symF(g_htmp);
    float* logf = symF(g_logf);
    float* logb = symF(g_logb);
    float* exf  = symF(g_exf);
    float* exb  = symF(g_exb);
    float* mf   = symF(g_mf);
    float* mb   = symF(g_mb);
    float* denf = symF(g_denf);
    float* denb = symF(g_denb);
    float* cols = symF(g_cols);
    __half* hhi = symH(g_hhi);
    __half* hlo = symH(g_hlo);
    __half* ehi = symH(g_ehi);
    __half* Wt  = symH(g_Wt);
    int* degf = symI(g_degf);  int* degb = symI(g_degb);
    int* offf = symI(g_offf);  int* offb = symI(g_offb);
    int* idxf = symI(g_idxf);  int* idxb = symI(g_idxb);

    float* hWs = hW;           float* hWd = hW + NF;
    float* hse = hW + 2*NF;    float* hWf_ = hW + 3*NF;
    float* hWb_ = hW + 4*NF;

    float* cse = cols;         float* cqe = cols + FF;
    float* sce = cols + 2*FF;  float* she = cols + 3*FF;
    float* csh = cols + 4*FF;  float* cqh = cols + 5*FF;
    float* sch = cols + 6*FF;  float* shh = cols + 7*FF;

    float* outH; float* outE;
    if (out_size >= NF + EF)      { outH = (float*)d_out; outE = (float*)d_out + NF; }
    else if (out_size == EF)      { outE = (float*)d_out; outH = htmp; }
    else                          { outH = (float*)d_out; outE = symF(g_dumpE); }

    cudaFuncSetAttribute(node_mma_k, cudaFuncAttributeMaxDynamicSharedMemorySize, SMEMB);
    cudaFuncSetAttribute(edge_mma_k, cudaFuncAttributeMaxDynamicSharedMemorySize, SMEMB);

    // weights (once)
    W6 w6; w6.p[0] = We; w6.p[1] = Ws; w6.p[2] = Wd; w6.p[3] = Wse; w6.p[4] = Wf; w6.p[5] = Wb;
    prep_w_k<<<(LL*6*WSZ)/256, 256>>>(w6, Wt);

    // inputs (once): h -> hi/lo; e -> hi only
    cvt_k<<<(NF/4 + 255)/256, 256>>>((const float4*)h0, (__half2*)hhi, (__half2*)hlo, NF/4);
    cvt_e_k<<<(EF/4 + 255)/256, 256>>>((const float4*)e0, (__half2*)ehi, EF/4);

    // CSR (once per launch)
    zero_deg_k<<<(NN+255)/256, 256>>>(degf, degb);
    hist_k<<<(EE+255)/256, 256>>>(src, dst, degf, degb);
    scan_k<<<1, 1024>>>(degf, degb, offf, offb);
    curcpy_k<<<(NN+255)/256, 256>>>(offf, offb, degf, degb);
    fill_k<<<(EE+255)/256, 256>>>(src, dst, degf, degb, idxf, idxb);

    for (int l = 0; l < LL; l++) {
        __half* WtL = Wt + (size_t)l * 6 * WSZ;
        int last = (l == LL-1);

        init_k<<<(NN + 255)/256, 256>>>(mf, mb, denf, denb, cols);

        // node GEMMs: h @ {Ws, Wd, Wself, Wf, Wb}  (1-term h-hi, fp32 out)
        O5 p; p.O[0] = hWs; p.O[1] = hWd; p.O[2] = hse; p.O[3] = hWf_; p.O[4] = hWb_;
        node_mma_k<<<dim3((NN + BM - 1)/BM, 1, 5), 512, SMEMB>>>(hhi, WtL, p, NN);

        // edge GEMM (1-term, ehi) + fused gather/logits/max/BN-stats, fp16 etmp out
        edge_mma_k<<<EE/BM, 512, SMEMB>>>(ehi, WtL, etmp, src, dst, hWs, hWd,
                                          attf + l*FF, attb + l*FF,
                                          logf, logb, mf, mb, cse, cqe);

        finalize_bn_k<<<1, 256>>>(cse, cqe, ge + l*FF, be + l*FF, 1.0f/EE, sce, she);
        exp_k<<<(EE + 255)/256, 256>>>(logf, logb, src, dst, mf, mb, exf, exb, denf, denb);

        // e residual (fp16 in-place, 16B-wide, fp32 out on last layer)
        residual_e_k<<<(EF/8 + 255)/256, 256>>>((uint4*)ehi, (const uint4*)etmp,
                                                sce, she, (float4*)outE, EF/8, last);

        // attention aggregation (CSR gather, fp32) + node update + BN stats
        gather_node_k<<<(NN + 31)/32, 256>>>(offf, idxf, offb, idxb, src, dst,
                                             exf, denf, exb, denb,
                                             (const float4*)hWf_, (const float4*)hWb_,
                                             (const float4*)hse, (float4*)htmp, csh, cqh);
        finalize_bn_k<<<1, 256>>>(csh, cqh, gh + l*FF, bh + l*FF, 1.0f/NN, sch, shh);

        // h residual (hi/lo carry, fp32 out on last layer)
        residual_h_k<<<(NF/4 + 255)/256, 256>>>((__half2*)hhi, (__half2*)hlo,
                                                (const float4*)htmp, sch, shh,
                                                (float4*)outH, NF/4, last);
    }
}

// round 15
// speedup vs baseline: 1.5129x; 1.0625x over previous
#include <cuda_runtime.h>
#include <cuda_fp16.h>
#include <math.h>
#include <stdint.h>

#define NN 50000
#define EE 800000
#define FF 256
#define NF (NN*FF)            // 12,800,000
#define EF (EE*FF)            // 204,800,000
#define LL 4
#define WK 256                // weight: single fp16 [N=256, K=256] K-major
#define WSZ (256*WK)

// GEMM tiling: BM=128, BN=256, BK=64, 512 threads (16 warps, 4x4)
#define BM 128
#define AST 72
#define BST 72
#define ABYTES (BM*AST*2)      // 18432
#define BBYTES (256*BST*2)     // 36864
#define BUFB (ABYTES + BBYTES) // 55296
#define SMEMB (2*BUFB)         // 110592

// ------------------------- scratch (device globals, no allocs) -------------
__device__ __half g_etmp[EF];      // fp16 e_tmp (streaming)
__device__ float g_hW[2*NF];       // fp32: hWs | hWd   (edge-epilogue gather path)
__device__ __half g_hWh[3*NF];     // fp16: hself | hWf | hWb (node gather path)
__device__ __half g_htmp[NF];      // fp16 h_tmp (streaming)
__device__ float g_logf[EE];
__device__ float g_logb[EE];
__device__ float g_exf[EE];
__device__ float g_exb[EE];
__device__ float g_mf[NN];
__device__ float g_mb[NN];
__device__ float g_denf[NN];
__device__ float g_denb[NN];
__device__ float g_cols[8*FF];
__device__ __half g_hhi[NF];
__device__ __half g_hlo[NF];
__device__ __half g_ehi[EF];       // e carried fp16 (hi only)
__device__ __half g_Wt[LL*6*WSZ];
__device__ float g_dumpE[EF];      // fallback-only fp32 sink
// CSR
__device__ int g_degf[NN];
__device__ int g_degb[NN];
__device__ int g_offf[NN+1];
__device__ int g_offb[NN+1];
__device__ int g_idxf[EE];
__device__ int g_idxb[EE];

// ------------------------- helpers -----------------------------------------
__device__ __forceinline__ uint32_t s2u(const void* p) {
    uint32_t a;
    asm("{ .reg .u64 t; cvta.to.shared.u64 t, %1; cvt.u32.u64 %0, t; }" : "=r"(a) : "l"(p));
    return a;
}
__device__ __forceinline__ void cp_async16(uint32_t saddr, const void* g) {
    asm volatile("cp.async.cg.shared.global [%0], [%1], 16;" :: "r"(saddr), "l"(g));
}
__device__ __forceinline__ void ldsm4(uint32_t addr, uint32_t& r0, uint32_t& r1,
                                      uint32_t& r2, uint32_t& r3) {
    asm volatile("ldmatrix.sync.aligned.m8n8.x4.shared.b16 {%0,%1,%2,%3}, [%4];"
                 : "=r"(r0), "=r"(r1), "=r"(r2), "=r"(r3) : "r"(addr));
}
__device__ __forceinline__ void mma16816(float* d, const uint32_t* a, const uint32_t* b) {
    asm volatile(
        "mma.sync.aligned.m16n8k16.row.col.f32.f16.f16.f32 "
        "{%0,%1,%2,%3}, {%4,%5,%6,%7}, {%8,%9}, {%0,%1,%2,%3};"
        : "+f"(d[0]), "+f"(d[1]), "+f"(d[2]), "+f"(d[3])
        : "r"(a[0]), "r"(a[1]), "r"(a[2]), "r"(a[3]), "r"(b[0]), "r"(b[1]));
}
__device__ __forceinline__ void atomicMaxF(float* a, float v) {
    int* ai = (int*)a;
    int old = __float_as_int(*a);
    while (__int_as_float(old) < v) {
        int prev = atomicCAS(ai, old, __float_as_int(v));
        if (prev == old) break;
        old = prev;
    }
}

// ------------------------- fp16 mma GEMM ------------------------------------
// MODE 0: node, fp32 C.  MODE 1: node, fp16 C.  MODE 2: edge (fused epilogue,
// fp16 C; adds gs[src]+gd[dst] fp32; logits + segment max + BN col stats).
// All single-term (A = hi only, 4 chunks of K=64).
template<int MODE>
__device__ __forceinline__ void mma_gemm(
    const __half* __restrict__ A,
    const __half* __restrict__ Bt, void* __restrict__ C, int M, int tile,
    const int* __restrict__ src, const int* __restrict__ dst,
    const float* __restrict__ gs, const float* __restrict__ gd,
    const float* __restrict__ af, const float* __restrict__ ab,
    float* __restrict__ logf, float* __restrict__ logb,
    float* __restrict__ mf, float* __restrict__ mb,
    float* __restrict__ cse, float* __restrict__ cqe)
{
    extern __shared__ __align__(16) char smem[];
    const uint32_t sb = s2u(smem);
    const int tid = threadIdx.x, wid = tid >> 5, lane = tid & 31;
    const int m0 = tile * BM;

    auto load_chunk = [&](int g, int buf) {
        const int acol = g << 6;
        const int kb = g << 6;
        const uint32_t a_s = sb + buf*BUFB;
        const uint32_t b_s = a_s + ABYTES;
        #pragma unroll
        for (int i = 0; i < 2; i++) {            // A: 128x64 halves
            int v = tid + (i << 9); int r = v >> 3, c16 = v & 7;
            uint32_t sa = a_s + (r*AST + (c16 << 3))*2;
            int gr = m0 + r;
            if (MODE == 2) {
                cp_async16(sa, A + (size_t)gr*256 + acol + (c16 << 3));
            } else {
                if (gr < M) cp_async16(sa, A + (size_t)gr*256 + acol + (c16 << 3));
                else asm volatile("st.shared.v4.b32 [%0], {%1,%1,%1,%1};" :: "r"(sa), "r"(0));
            }
        }
        #pragma unroll
        for (int i = 0; i < 4; i++) {            // B: 256x64 halves
            int v = tid + (i << 9); int r = v >> 3, c16 = v & 7;
            cp_async16(b_s + (r*BST + (c16 << 3))*2, Bt + r*WK + kb + (c16 << 3));
        }
        asm volatile("cp.async.commit_group;");
    };

    const int wm = (wid & 3) << 5;               // 0..96
    const int wn = (wid >> 2) << 6;              // 0,64,128,192
    uint32_t a_off[2];
    #pragma unroll
    for (int im = 0; im < 2; im++)
        a_off[im] = ((wm + im*16 + (lane & 15))*AST + ((lane >> 4) << 3))*2;
    const uint32_t b_off = ((wn + ((lane >> 4) << 3) + (lane & 7))*BST
                           + (((lane >> 3) & 1) << 3))*2;

    float acc[2][8][4];
    #pragma unroll
    for (int im = 0; im < 2; im++)
        #pragma unroll
        for (int j = 0; j < 8; j++)
            #pragma unroll
            for (int q = 0; q < 4; q++) acc[im][j][q] = 0.f;

    load_chunk(0, 0);
    int buf = 0;
    for (int c = 0; c < 4; c++) {
        if (c < 3) {
            load_chunk(c + 1, buf ^ 1);
            asm volatile("cp.async.wait_group 1;");
        } else {
            asm volatile("cp.async.wait_group 0;");
        }
        __syncthreads();
        const uint32_t a_s = sb + buf*BUFB;
        const uint32_t b_s = a_s + ABYTES;
        #pragma unroll
        for (int ks = 0; ks < 4; ks++) {
            const uint32_t kh2 = (ks << 4)*2;
            uint32_t a[2][4], b[8][2];
            ldsm4(a_s + a_off[0] + kh2, a[0][0], a[0][1], a[0][2], a[0][3]);
            ldsm4(a_s + a_off[1] + kh2, a[1][0], a[1][1], a[1][2], a[1][3]);
            #pragma unroll
            for (int jp = 0; jp < 4; jp++)
                ldsm4(b_s + b_off + jp*(16*BST*2) + kh2,
                      b[2*jp][0], b[2*jp][1], b[2*jp+1][0], b[2*jp+1][1]);
            #pragma unroll
            for (int im = 0; im < 2; im++)
                #pragma unroll
                for (int j = 0; j < 8; j++)
                    mma16816(acc[im][j], a[im], b[j]);
        }
        __syncthreads();
        buf ^= 1;
    }

    // ---------------- epilogue ----------------
    const int gr0 = lane >> 2;
    const int cl0 = (lane & 3) << 1;

    if (MODE == 0) {
        float* Cf = (float*)C;
        #pragma unroll
        for (int im = 0; im < 2; im++)
            #pragma unroll
            for (int half = 0; half < 2; half++) {
                int gm = m0 + wm + im*16 + gr0 + half*8;
                if (gm >= M) continue;
                #pragma unroll
                for (int j = 0; j < 8; j++) {
                    int col = wn + (j << 3) + cl0;
                    *(float2*)(Cf + (size_t)gm*256 + col) =
                        make_float2(acc[im][j][half*2], acc[im][j][half*2+1]);
                }
            }
        return;
    }
    if (MODE == 1) {
        __half* Ch = (__half*)C;
        #pragma unroll
        for (int im = 0; im < 2; im++)
            #pragma unroll
            for (int half = 0; half < 2; half++) {
                int gm = m0 + wm + im*16 + gr0 + half*8;
                if (gm >= M) continue;
                #pragma unroll
                for (int j = 0; j < 8; j++) {
                    int col = wn + (j << 3) + cl0;
                    *(__half2*)(Ch + (size_t)gm*256 + col) =
                        __float22half2_rn(make_float2(acc[im][j][half*2], acc[im][j][half*2+1]));
                }
            }
        return;
    }

    // MODE 2 (edge): fused gather + logits + BN stats, fp16 C store
    __half* Ch = (__half*)C;
    float* sred = (float*)smem;   // [0:128) rowf | [128:256) rowb | [256:512) cs | [512:768) cq
    for (int i = tid; i < 768; i += 512) sred[i] = 0.f;
    __syncthreads();

    float cs[16], cq[16];
    #pragma unroll
    for (int q = 0; q < 16; q++) { cs[q] = 0.f; cq[q] = 0.f; }

    #pragma unroll
    for (int im = 0; im < 2; im++)
        #pragma unroll
        for (int half = 0; half < 2; half++) {
            int rloc = wm + im*16 + gr0 + half*8;
            int gm = m0 + rloc;
            int s = src[gm], d = dst[gm];
            float pf = 0.f, pb = 0.f;
            #pragma unroll
            for (int j = 0; j < 8; j++) {
                int col = wn + (j << 3) + cl0;
                float2 o = make_float2(acc[im][j][half*2], acc[im][j][half*2+1]);
                float2 x = *(const float2*)(gs + (size_t)s*256 + col);
                float2 y = *(const float2*)(gd + (size_t)d*256 + col);
                o.x += x.x + y.x; o.y += x.y + y.y;
                *(__half2*)(Ch + (size_t)gm*256 + col) = __float22half2_rn(o);
                pf += o.x*__ldg(af+col) + o.y*__ldg(af+col+1);
                pb += o.x*__ldg(ab+col) + o.y*__ldg(ab+col+1);
                cs[j*2]   += o.x; cs[j*2+1] += o.y;
                cq[j*2]   += o.x*o.x; cq[j*2+1] += o.y*o.y;
            }
            pf += __shfl_xor_sync(0xFFFFFFFFu, pf, 1);
            pf += __shfl_xor_sync(0xFFFFFFFFu, pf, 2);
            pb += __shfl_xor_sync(0xFFFFFFFFu, pb, 1);
            pb += __shfl_xor_sync(0xFFFFFFFFu, pb, 2);
            if ((lane & 3) == 0) {
                atomicAdd(&sred[rloc], pf);
                atomicAdd(&sred[128 + rloc], pb);
            }
        }
    #pragma unroll
    for (int q = 0; q < 16; q++) {
        cs[q] += __shfl_xor_sync(0xFFFFFFFFu, cs[q], 4);
        cs[q] += __shfl_xor_sync(0xFFFFFFFFu, cs[q], 8);
        cs[q] += __shfl_xor_sync(0xFFFFFFFFu, cs[q], 16);
        cq[q] += __shfl_xor_sync(0xFFFFFFFFu, cq[q], 4);
        cq[q] += __shfl_xor_sync(0xFFFFFFFFu, cq[q], 8);
        cq[q] += __shfl_xor_sync(0xFFFFFFFFu, cq[q], 16);
    }
    if (lane < 4) {
        #pragma unroll
        for (int j = 0; j < 8; j++) {
            int col = wn + (j << 3) + ((lane & 3) << 1);
            atomicAdd(&sred[256 + col],     cs[j*2]);
            atomicAdd(&sred[256 + col + 1], cs[j*2+1]);
            atomicAdd(&sred[512 + col],     cq[j*2]);
            atomicAdd(&sred[512 + col + 1], cq[j*2+1]);
        }
    }
    __syncthreads();
    if (tid < 128) {
        int gm = m0 + tid;
        float lf = sred[tid];       lf = lf > 0.f ? lf : 0.2f*lf;
        float lb = sred[128 + tid]; lb = lb > 0.f ? lb : 0.2f*lb;
        logf[gm] = lf; logb[gm] = lb;
        atomicMaxF(&mf[dst[gm]], lf);
        atomicMaxF(&mb[src[gm]], lb);
    } else if (tid < 384) {
        int col = tid - 128;
        atomicAdd(&cse[col], sred[256 + col]);
        atomicAdd(&cqe[col], sred[512 + col]);
    }
}

struct O2 { float* O[2]; };
struct O3 { __half* O[3]; };

__global__ __launch_bounds__(512)
void node_mma_f_k(const __half* __restrict__ Ahi,
                  const __half* __restrict__ WtL, O2 p, int M) {
    // z=0 -> Ws (weight idx 1), z=1 -> Wd (idx 2)
    mma_gemm<0>(Ahi, WtL + (size_t)(blockIdx.z + 1)*WSZ, p.O[blockIdx.z],
                M, blockIdx.x, nullptr, nullptr, nullptr, nullptr,
                nullptr, nullptr, nullptr, nullptr, nullptr, nullptr, nullptr, nullptr);
}

__global__ __launch_bounds__(512)
void node_mma_h_k(const __half* __restrict__ Ahi,
                  const __half* __restrict__ WtL, O3 p, int M) {
    // z=0 -> Wself (idx 3), z=1 -> Wf (idx 4), z=2 -> Wb (idx 5)
    mma_gemm<1>(Ahi, WtL + (size_t)(blockIdx.z + 3)*WSZ, p.O[blockIdx.z],
                M, blockIdx.x, nullptr, nullptr, nullptr, nullptr,
                nullptr, nullptr, nullptr, nullptr, nullptr, nullptr, nullptr, nullptr);
}

__global__ __launch_bounds__(512)
void edge_mma_k(const __half* __restrict__ Ahi,
                const __half* __restrict__ WtL, __half* __restrict__ C,
                const int* __restrict__ src, const int* __restrict__ dst,
                const float* __restrict__ gs, const float* __restrict__ gd,
                const float* __restrict__ af, const float* __restrict__ ab,
                float* __restrict__ logf, float* __restrict__ logb,
                float* __restrict__ mf, float* __restrict__ mb,
                float* __restrict__ cse, float* __restrict__ cqe) {
    mma_gemm<2>(Ahi, WtL, C, EE, blockIdx.x, src, dst, gs, gd,
                af, ab, logf, logb, mf, mb, cse, cqe);
}

// ------------------------- prep / CSR ---------------------------------------
struct W6 { const float* p[6]; };

__global__ void prep_w_k(W6 w, __half* __restrict__ out) {
    long idx = (long)blockIdx.x * 256 + threadIdx.x;      // LL*6*256*256
    int k = (int)(idx % WK); long t = idx / WK;
    int n = (int)(t % 256);  t /= 256;
    int wi = (int)(t % 6);   int l = (int)(t / 6);
    out[idx] = __float2half(w.p[wi][((size_t)l * 256 + k) * 256 + n]);
}

__global__ void cvt_k(const float4* __restrict__ x, __half2* __restrict__ hi,
                      __half2* __restrict__ lo, int n4) {
    int i = blockIdx.x * blockDim.x + threadIdx.x;
    if (i >= n4) return;
    float4 v = x[i];
    __half h0 = __float2half(v.x), h1 = __float2half(v.y);
    __half h2 = __float2half(v.z), h3 = __float2half(v.w);
    hi[2*i]   = __halves2half2(h0, h1);
    hi[2*i+1] = __halves2half2(h2, h3);
    lo[2*i]   = __halves2half2(__float2half(v.x - __half2float(h0)),
                               __float2half(v.y - __half2float(h1)));
    lo[2*i+1] = __halves2half2(__float2half(v.z - __half2float(h2)),
                               __float2half(v.w - __half2float(h3)));
}

__global__ void cvt_e_k(const float4* __restrict__ x, __half2* __restrict__ hi, int n4) {
    int i = blockIdx.x * blockDim.x + threadIdx.x;
    if (i >= n4) return;
    float4 v = x[i];
    hi[2*i]   = __float22half2_rn(make_float2(v.x, v.y));
    hi[2*i+1] = __float22half2_rn(make_float2(v.z, v.w));
}

__global__ void zero_deg_k(int* df, int* db) {
    int i = blockIdx.x*blockDim.x + threadIdx.x;
    if (i < NN) { df[i] = 0; db[i] = 0; }
}
__global__ void hist_k(const int* __restrict__ src, const int* __restrict__ dst,
                       int* df, int* db) {
    int e = blockIdx.x*blockDim.x + threadIdx.x;
    if (e >= EE) return;
    atomicAdd(&df[dst[e]], 1);
    atomicAdd(&db[src[e]], 1);
}
__global__ void scan_k(const int* __restrict__ degf, const int* __restrict__ degb,
                       int* offf, int* offb) {
    __shared__ int s[1024];
    for (int arr = 0; arr < 2; arr++) {
        const int* deg = arr ? degb : degf;
        int* off = arr ? offb : offf;
        int carry = 0;
        if (threadIdx.x == 0) off[0] = 0;
        for (int base = 0; base < NN; base += 1024) {
            int i = base + threadIdx.x;
            s[threadIdx.x] = (i < NN) ? deg[i] : 0;
            __syncthreads();
            for (int d = 1; d < 1024; d <<= 1) {
                int t = (threadIdx.x >= d) ? s[threadIdx.x - d] : 0;
                __syncthreads();
                s[threadIdx.x] += t;
                __syncthreads();
            }
            if (i < NN) off[i+1] = carry + s[threadIdx.x];
            carry += s[1023];
            __syncthreads();
        }
    }
}
__global__ void curcpy_k(const int* offf, const int* offb, int* curf, int* curb) {
    int i = blockIdx.x*blockDim.x + threadIdx.x;
    if (i < NN) { curf[i] = offf[i]; curb[i] = offb[i]; }
}
__global__ void fill_k(const int* __restrict__ src, const int* __restrict__ dst,
                       int* curf, int* curb, int* idxf, int* idxb) {
    int e = blockIdx.x*blockDim.x + threadIdx.x;
    if (e >= EE) return;
    idxf[atomicAdd(&curf[dst[e]], 1)] = e;
    idxb[atomicAdd(&curb[src[e]], 1)] = e;
}

// ------------------------- per-layer small kernels --------------------------
__global__ void init_k(float* mf, float* mb, float* denf, float* denb, float* cols) {
    int i = blockIdx.x*blockDim.x + threadIdx.x;
    if (i < NN) { mf[i] = -INFINITY; mb[i] = -INFINITY; denf[i] = 0.f; denb[i] = 0.f; }
    if (i < 8*FF) cols[i] = 0.f;
}

__global__ void finalize_bn_k(const float* __restrict__ colsum, const float* __restrict__ colsumsq,
                              const float* __restrict__ g, const float* __restrict__ b,
                              float invM, float* __restrict__ scale, float* __restrict__ shift) {
    int f = threadIdx.x;
    float mean = colsum[f] * invM;
    float var  = colsumsq[f] * invM - mean*mean;
    float sc   = g[f] * rsqrtf(var + 1e-5f);
    scale[f] = sc;
    shift[f] = b[f] - mean * sc;
}

__global__ void exp_k(const float* __restrict__ logf, const float* __restrict__ logb,
                      const int* __restrict__ src, const int* __restrict__ dst,
                      const float* __restrict__ mf, const float* __restrict__ mb,
                      float* __restrict__ exf, float* __restrict__ exb,
                      float* __restrict__ denf, float* __restrict__ denb) {
    int i = blockIdx.x*blockDim.x + threadIdx.x;
    if (i >= EE) return;
    int d = dst[i], s = src[i];
    float ef = expf(logf[i] - mf[d]);
    float eb = expf(logb[i] - mb[s]);
    exf[i] = ef; exb[i] = eb;
    atomicAdd(&denf[d], ef);
    atomicAdd(&denb[s], eb);
}

// e residual: ehi = fp16(ehi + relu(etmp*scale+shift)); 16B-wide; fp32 out on last
__global__ void residual_e_k(uint4* __restrict__ hi, const uint4* __restrict__ x,
                             const float* __restrict__ scale, const float* __restrict__ shift,
                             float4* __restrict__ outF, int n8, int writeF) {
    int i = blockIdx.x*blockDim.x + threadIdx.x;
    if (i >= n8) return;
    int c8 = i & 31;
    uint4 hv = hi[i];
    uint4 xv = x[i];
    const __half2* hp = (const __half2*)&hv;
    const __half2* xp = (const __half2*)&xv;
    float4 sc0 = ((const float4*)scale)[c8*2],  sc1 = ((const float4*)scale)[c8*2+1];
    float4 sh0 = ((const float4*)shift)[c8*2],  sh1 = ((const float4*)shift)[c8*2+1];
    float r[8];
    {
        float2 a = __half22float2(hp[0]), b = __half22float2(xp[0]);
        r[0] = a.x + fmaxf(b.x*sc0.x + sh0.x, 0.f);
        r[1] = a.y + fmaxf(b.y*sc0.y + sh0.y, 0.f);
        a = __half22float2(hp[1]); b = __half22float2(xp[1]);
        r[2] = a.x + fmaxf(b.x*sc0.z + sh0.z, 0.f);
        r[3] = a.y + fmaxf(b.y*sc0.w + sh0.w, 0.f);
        a = __half22float2(hp[2]); b = __half22float2(xp[2]);
        r[4] = a.x + fmaxf(b.x*sc1.x + sh1.x, 0.f);
        r[5] = a.y + fmaxf(b.y*sc1.y + sh1.y, 0.f);
        a = __half22float2(hp[3]); b = __half22float2(xp[3]);
        r[6] = a.x + fmaxf(b.x*sc1.z + sh1.z, 0.f);
        r[7] = a.y + fmaxf(b.y*sc1.w + sh1.w, 0.f);
    }
    uint4 ov;
    __half2* op = (__half2*)&ov;
    op[0] = __float22half2_rn(make_float2(r[0], r[1]));
    op[1] = __float22half2_rn(make_float2(r[2], r[3]));
    op[2] = __float22half2_rn(make_float2(r[4], r[5]));
    op[3] = __float22half2_rn(make_float2(r[6], r[7]));
    hi[i] = ov;
    if (writeF) {
        outF[2*i]   = make_float4(r[0], r[1], r[2], r[3]);
        outF[2*i+1] = make_float4(r[4], r[5], r[6], r[7]);
    }
}

// h residual: hi/lo carry, fp16 x (htmp, uint2 = 4 halves); fp32 out on last
__global__ void residual_h_k(__half2* hi, __half2* lo, const uint2* __restrict__ x,
                             const float* __restrict__ scale, const float* __restrict__ shift,
                             float4* __restrict__ outF, int n4, int writeF) {
    int i = blockIdx.x*blockDim.x + threadIdx.x;
    if (i >= n4) return;
    int c4 = i & 63;
    __half2 a0 = hi[2*i], a1 = hi[2*i+1], b0 = lo[2*i], b1 = lo[2*i+1];
    float4 base;
    base.x = __half2float(a0.x) + __half2float(b0.x);
    base.y = __half2float(a0.y) + __half2float(b0.y);
    base.z = __half2float(a1.x) + __half2float(b1.x);
    base.w = __half2float(a1.y) + __half2float(b1.y);
    uint2 xu = x[i];
    float2 x0 = __half22float2(*(const __half2*)&xu.x);
    float2 x1 = __half22float2(*(const __half2*)&xu.y);
    float4 sc = ((const float4*)scale)[c4];
    float4 sh = ((const float4*)shift)[c4];
    float4 r;
    r.x = base.x + fmaxf(x0.x*sc.x + sh.x, 0.f);
    r.y = base.y + fmaxf(x0.y*sc.y + sh.y, 0.f);
    r.z = base.z + fmaxf(x1.x*sc.z + sh.z, 0.f);
    r.w = base.w + fmaxf(x1.y*sc.w + sh.w, 0.f);
    __half h0 = __float2half(r.x), h1 = __float2half(r.y);
    __half h2 = __float2half(r.z), h3 = __float2half(r.w);
    hi[2*i]   = __halves2half2(h0, h1);
    hi[2*i+1] = __halves2half2(h2, h3);
    lo[2*i]   = __halves2half2(__float2half(r.x - __half2float(h0)),
                               __float2half(r.y - __half2float(h1)));
    lo[2*i+1] = __halves2half2(__float2half(r.z - __half2float(h2)),
                               __float2half(r.w - __half2float(h3)));
    if (writeF) outF[i] = r;
}

// CSR gather aggregation + node update + BN stats.
// hself/hWf/hWb fp16, uint2 loads (4 halves = 8B, 64 threads cover a row).
__global__ void gather_node_k(
    const int* __restrict__ offf, const int* __restrict__ idxf,
    const int* __restrict__ offb, const int* __restrict__ idxb,
    const int* __restrict__ src, const int* __restrict__ dst,
    const float* __restrict__ exf, const float* __restrict__ denf,
    const float* __restrict__ exb, const float* __restrict__ denb,
    const uint2* __restrict__ hWf, const uint2* __restrict__ hWb,
    const uint2* __restrict__ hself, uint2* __restrict__ htmp,
    float* __restrict__ colsum, float* __restrict__ colsumsq) {
    __shared__ float4 scs[256], scq[256];
    const int sub = threadIdx.x >> 6, c = threadIdx.x & 63;
    float4 csum = make_float4(0,0,0,0), csq = make_float4(0,0,0,0);
    #pragma unroll 1
    for (int nn = 0; nn < 8; nn++) {
        int node = blockIdx.x*32 + sub*8 + nn;
        if (node >= NN) break;
        float invf = 1.f/(denf[node] + 1e-9f);
        float invb = 1.f/(denb[node] + 1e-9f);
        uint2 su = hself[(size_t)node*64 + c];
        float2 s0 = __half22float2(*(const __half2*)&su.x);
        float2 s1 = __half22float2(*(const __half2*)&su.y);
        float4 acc = make_float4(s0.x, s0.y, s1.x, s1.y);
        int e0 = offf[node], e1 = offf[node+1];
        for (int i = e0; i < e1; i++) {
            int e = idxf[i];
            float a = exf[e]*invf;
            uint2 u = hWf[(size_t)src[e]*64 + c];
            float2 v0 = __half22float2(*(const __half2*)&u.x);
            float2 v1 = __half22float2(*(const __half2*)&u.y);
            acc.x += a*v0.x; acc.y += a*v0.y; acc.z += a*v1.x; acc.w += a*v1.y;
        }
        e0 = offb[node]; e1 = offb[node+1];
        for (int i = e0; i < e1; i++) {
            int e = idxb[i];
            float a = exb[e]*invb;
            uint2 u = hWb[(size_t)dst[e]*64 + c];
            float2 v0 = __half22float2(*(const __half2*)&u.x);
            float2 v1 = __half22float2(*(const __half2*)&u.y);
            acc.x += a*v0.x; acc.y += a*v0.y; acc.z += a*v1.x; acc.w += a*v1.y;
        }
        uint2 ou;
        *(__half2*)&ou.x = __float22half2_rn(make_float2(acc.x, acc.y));
        *(__half2*)&ou.y = __float22half2_rn(make_float2(acc.z, acc.w));
        htmp[(size_t)node*64 + c] = ou;
        csum.x += acc.x; csum.y += acc.y; csum.z += acc.z; csum.w += acc.w;
        csq.x += acc.x*acc.x; csq.y += acc.y*acc.y; csq.z += acc.z*acc.z; csq.w += acc.w*acc.w;
    }
    scs[threadIdx.x] = csum; scq[threadIdx.x] = csq;
    __syncthreads();
    if (sub == 0) {
        float4 s = scs[c], q = scq[c];
        #pragma unroll
        for (int k = 1; k < 4; k++) {
            float4 t = scs[k*64 + c], u = scq[k*64 + c];
            s.x += t.x; s.y += t.y; s.z += t.z; s.w += t.w;
            q.x += u.x; q.y += u.y; q.z += u.z; q.w += u.w;
        }
        atomicAdd(&colsum[c*4+0], s.x); atomicAdd(&colsum[c*4+1], s.y);
        atomicAdd(&colsum[c*4+2], s.z); atomicAdd(&colsum[c*4+3], s.w);
        atomicAdd(&colsumsq[c*4+0], q.x); atomicAdd(&colsumsq[c*4+1], q.y);
        atomicAdd(&colsumsq[c*4+2], q.z); atomicAdd(&colsumsq[c*4+3], q.w);
    }
}

// ------------------------- host orchestration ------------------------------
static float* symF(const void* s) { void* p = nullptr; cudaGetSymbolAddress(&p, s); return (float*)p; }
static int*   symI(const void* s) { void* p = nullptr; cudaGetSymbolAddress(&p, s); return (int*)p; }
static __half* symH(const void* s) { void* p = nullptr; cudaGetSymbolAddress(&p, s); return (__half*)p; }

extern "C" void kernel_launch(void* const* d_in, const int* in_sizes, int n_in,
                              void* d_out, int out_size) {
    const float* h0   = (const float*)d_in[0];
    const float* e0   = (const float*)d_in[1];
    const int*   src  = (const int*)d_in[2];
    const int*   dst  = (const int*)d_in[3];
    const float* We   = (const float*)d_in[4];
    const float* Ws   = (const float*)d_in[5];
    const float* Wd   = (const float*)d_in[6];
    const float* Wse  = (const float*)d_in[7];
    const float* Wf   = (const float*)d_in[8];
    const float* Wb   = (const float*)d_in[9];
    const float* attf = (const float*)d_in[10];
    const float* attb = (const float*)d_in[11];
    const float* ge   = (const float*)d_in[12];
    const float* be   = (const float*)d_in[13];
    const float* gh   = (const float*)d_in[14];
    const float* bh   = (const float*)d_in[15];

    __half* etmp = symH(g_etmp);
    float* hW    = symF(g_hW);
    __half* hWh  = symH(g_hWh);
    __half* htmp = symH(g_htmp);
    float* logf = symF(g_logf);
    float* logb = symF(g_logb);
    float* exf  = symF(g_exf);
    float* exb  = symF(g_exb);
    float* mf   = symF(g_mf);
    float* mb   = symF(g_mb);
    float* denf = symF(g_denf);
    float* denb = symF(g_denb);
    float* cols = symF(g_cols);
    __half* hhi = symH(g_hhi);
    __half* hlo = symH(g_hlo);
    __half* ehi = symH(g_ehi);
    __half* Wt  = symH(g_Wt);
    int* degf = symI(g_degf);  int* degb = symI(g_degb);
    int* offf = symI(g_offf);  int* offb = symI(g_offb);
    int* idxf = symI(g_idxf);  int* idxb = symI(g_idxb);

    float* hWs = hW;           float* hWd = hW + NF;
    __half* hse16 = hWh;       __half* hWf16 = hWh + NF;
    __half* hWb16 = hWh + 2*NF;

    float* cse = cols;         float* cqe = cols + FF;
    float* sce = cols + 2*FF;  float* she = cols + 3*FF;
    float* csh = cols + 4*FF;  float* cqh = cols + 5*FF;
    float* sch = cols + 6*FF;  float* shh = cols + 7*FF;

    float* outH; float* outE;
    float* htmpF = symF(g_dumpE);           // reuse sink as fp32 area when needed
    if (out_size >= NF + EF)      { outH = (float*)d_out; outE = (float*)d_out + NF; }
    else if (out_size == EF)      { outE = (float*)d_out; outH = htmpF; }
    else                          { outH = (float*)d_out; outE = htmpF; }

    cudaFuncSetAttribute(node_mma_f_k, cudaFuncAttributeMaxDynamicSharedMemorySize, SMEMB);
    cudaFuncSetAttribute(node_mma_h_k, cudaFuncAttributeMaxDynamicSharedMemorySize, SMEMB);
    cudaFuncSetAttribute(edge_mma_k,   cudaFuncAttributeMaxDynamicSharedMemorySize, SMEMB);

    // weights (once)
    W6 w6; w6.p[0] = We; w6.p[1] = Ws; w6.p[2] = Wd; w6.p[3] = Wse; w6.p[4] = Wf; w6.p[5] = Wb;
    prep_w_k<<<(LL*6*WSZ)/256, 256>>>(w6, Wt);

    // inputs (once): h -> hi/lo; e -> hi only
    cvt_k<<<(NF/4 + 255)/256, 256>>>((const float4*)h0, (__half2*)hhi, (__half2*)hlo, NF/4);
    cvt_e_k<<<(EF/4 + 255)/256, 256>>>((const float4*)e0, (__half2*)ehi, EF/4);

    // CSR (once per launch)
    zero_deg_k<<<(NN+255)/256, 256>>>(degf, degb);
    hist_k<<<(EE+255)/256, 256>>>(src, dst, degf, degb);
    scan_k<<<1, 1024>>>(degf, degb, offf, offb);
    curcpy_k<<<(NN+255)/256, 256>>>(offf, offb, degf, degb);
    fill_k<<<(EE+255)/256, 256>>>(src, dst, degf, degb, idxf, idxb);

    for (int l = 0; l < LL; l++) {
        __half* WtL = Wt + (size_t)l * 6 * WSZ;
        int last = (l == LL-1);

        init_k<<<(NN + 255)/256, 256>>>(mf, mb, denf, denb, cols);

        // node GEMMs (1-term h-hi): {Ws,Wd} fp32 out; {Wself,Wf,Wb} fp16 out
        O2 pf2; pf2.O[0] = hWs; pf2.O[1] = hWd;
        node_mma_f_k<<<dim3((NN + BM - 1)/BM, 1, 2), 512, SMEMB>>>(hhi, WtL, pf2, NN);
        O3 ph3; ph3.O[0] = hse16; ph3.O[1] = hWf16; ph3.O[2] = hWb16;
        node_mma_h_k<<<dim3((NN + BM - 1)/BM, 1, 3), 512, SMEMB>>>(hhi, WtL, ph3, NN);

        // edge GEMM (1-term, ehi) + fused gather/logits/max/BN-stats, fp16 etmp out
        edge_mma_k<<<EE/BM, 512, SMEMB>>>(ehi, WtL, etmp, src, dst, hWs, hWd,
                                          attf + l*FF, attb + l*FF,
                                          logf, logb, mf, mb, cse, cqe);

        finalize_bn_k<<<1, 256>>>(cse, cqe, ge + l*FF, be + l*FF, 1.0f/EE, sce, she);
        exp_k<<<(EE + 255)/256, 256>>>(logf, logb, src, dst, mf, mb, exf, exb, denf, denb);

        // e residual (fp16 in-place, 16B-wide, fp32 out on last layer)
        residual_e_k<<<(EF/8 + 255)/256, 256>>>((uint4*)ehi, (const uint4*)etmp,
                                                sce, she, (float4*)outE, EF/8, last);

        // attention aggregation (CSR gather, fp16 8B loads) + node update + BN stats
        gather_node_k<<<(NN + 31)/32, 256>>>(offf, idxf, offb, idxb, src, dst,
                                             exf, denf, exb, denb,
                                             (const uint2*)hWf16, (const uint2*)hWb16,
                                             (const uint2*)hse16, (uint2*)htmp, csh, cqh);
        finalize_bn_k<<<1, 256>>>(csh, cqh, gh + l*FF, bh + l*FF, 1.0f/NN, sch, shh);

        // h residual (hi/lo carry, fp16 htmp in, fp32 out on last layer)
        residual_h_k<<<(NF/4 + 255)/256, 256>>>((__half2*)hhi, (__half2*)hlo,
                                                (const uint2*)htmp, sch, shh,
                                                (float4*)outH, NF/4, last);
    }
}

// round 16
// speedup vs baseline: 1.5211x; 1.0055x over previous
#include <cuda_runtime.h>
#include <cuda_fp16.h>
#include <math.h>
#include <stdint.h>

#define NN 50000
#define EE 800000
#define FF 256
#define NF (NN*FF)            // 12,800,000
#define EF (EE*FF)            // 204,800,000
#define LL 4
#define WK 256                // weight: single fp16 [N=256, K=256] K-major
#define WSZ (256*WK)

// GEMM tiling: BM=128, BN=256, BK=64, 512 threads (16 warps, 4x4)
#define BM 128
#define AST 72
#define BST 72
#define ABYTES (BM*AST*2)      // 18432 (one 64-col A chunk)
#define BBYTES (256*BST*2)     // 36864
#define BUFB (ABYTES + BBYTES) // 55296
#define SMEMB (2*BUFB)         // 110592 (edge kernel)
#define AFULL (4*ABYTES)       // 73728 (full A tile, node kernel)
#define SMEM_NODE (AFULL + 2*BBYTES)  // 147456

#define EXPB ((EE + 255)/256)  // 3125 exp blocks in combined kernel
#define RESEB (EF/8/1024)      // 25000 residual-e blocks (4 x uint4 per thread)
#define RESHB (NF/4/1024)      // 3125 residual-h blocks

// ------------------------- scratch (device globals, no allocs) -------------
__device__ __half g_etmp[EF];      // fp16 e_tmp (streaming)
__device__ float g_hW[2*NF];       // fp32: hWs | hWd   (edge-epilogue gather path)
__device__ __half g_hWh[3*NF];     // fp16: hself | hWf | hWb (node gather path)
__device__ __half g_htmp[NF];      // fp16 h_tmp (streaming)
__device__ float g_logf[EE];
__device__ float g_logb[EE];
__device__ float g_exf[EE];
__device__ float g_exb[EE];
__device__ float g_mf[NN];
__device__ float g_mb[NN];
__device__ float g_denf[NN];
__device__ float g_denb[NN];
__device__ float g_cols[8*FF];
__device__ __half g_hhi[NF];
__device__ __half g_hlo[NF];
__device__ __half g_ehi[EF];       // e carried fp16 (hi only)
__device__ __half g_Wt[LL*6*WSZ];
__device__ float g_dumpE[EF];      // fallback-only fp32 sink
// CSR
__device__ int g_degf[NN];
__device__ int g_degb[NN];
__device__ int g_offf[NN+1];
__device__ int g_offb[NN+1];
__device__ int g_idxf[EE];
__device__ int g_idxb[EE];

// ------------------------- helpers -----------------------------------------
__device__ __forceinline__ uint32_t s2u(const void* p) {
    uint32_t a;
    asm("{ .reg .u64 t; cvta.to.shared.u64 t, %1; cvt.u32.u64 %0, t; }" : "=r"(a) : "l"(p));
    return a;
}
__device__ __forceinline__ void cp_async16(uint32_t saddr, const void* g) {
    asm volatile("cp.async.cg.shared.global [%0], [%1], 16;" :: "r"(saddr), "l"(g));
}
__device__ __forceinline__ void ldsm4(uint32_t addr, uint32_t& r0, uint32_t& r1,
                                      uint32_t& r2, uint32_t& r3) {
    asm volatile("ldmatrix.sync.aligned.m8n8.x4.shared.b16 {%0,%1,%2,%3}, [%4];"
                 : "=r"(r0), "=r"(r1), "=r"(r2), "=r"(r3) : "r"(addr));
}
__device__ __forceinline__ void mma16816(float* d, const uint32_t* a, const uint32_t* b) {
    asm volatile(
        "mma.sync.aligned.m16n8k16.row.col.f32.f16.f16.f32 "
        "{%0,%1,%2,%3}, {%4,%5,%6,%7}, {%8,%9}, {%0,%1,%2,%3};"
        : "+f"(d[0]), "+f"(d[1]), "+f"(d[2]), "+f"(d[3])
        : "r"(a[0]), "r"(a[1]), "r"(a[2]), "r"(a[3]), "r"(b[0]), "r"(b[1]));
}
__device__ __forceinline__ void atomicMaxF(float* a, float v) {
    int* ai = (int*)a;
    int old = __float_as_int(*a);
    while (__int_as_float(old) < v) {
        int prev = atomicCAS(ai, old, __float_as_int(v));
        if (prev == old) break;
        old = prev;
    }
}

// ------------------------- fused node GEMM (5 weights, A-resident) ----------
// C_w[tile*128..+128, 0..256) = A@W_w for w in 0..4 (Ws,Wd fp32; Wself,Wf,Wb fp16)
struct O5h { void* O[5]; };

__global__ __launch_bounds__(512)
void node_mma_all_k(const __half* __restrict__ A, const __half* __restrict__ WtL,
                    O5h p, int M) {
    extern __shared__ __align__(16) char smem[];
    const uint32_t sb = s2u(smem);
    const int tid = threadIdx.x, wid = tid >> 5, lane = tid & 31;
    const int m0 = blockIdx.x * BM;

    // Load ALL 4 A chunks once (resident for all 5 weights)
    #pragma unroll
    for (int g = 0; g < 4; g++) {
        #pragma unroll
        for (int i = 0; i < 2; i++) {
            int v = tid + (i << 9); int r = v >> 3, c16 = v & 7;
            uint32_t sa = sb + g*ABYTES + (r*AST + (c16 << 3))*2;
            int gr = m0 + r;
            if (gr < M) cp_async16(sa, A + (size_t)gr*256 + (g << 6) + (c16 << 3));
            else asm volatile("st.shared.v4.b32 [%0], {%1,%1,%1,%1};" :: "r"(sa), "r"(0));
        }
    }
    asm volatile("cp.async.commit_group;");

    auto load_B = [&](int t, int buf) {
        int w = t >> 2, g = t & 3;
        const __half* Bt = WtL + (size_t)(w + 1)*WSZ;   // weight idx 1..5
        uint32_t b_s = sb + AFULL + buf*BBYTES;
        #pragma unroll
        for (int i = 0; i < 4; i++) {
            int v = tid + (i << 9); int r = v >> 3, c16 = v & 7;
            cp_async16(b_s + (r*BST + (c16 << 3))*2, Bt + r*WK + (g << 6) + (c16 << 3));
        }
        asm volatile("cp.async.commit_group;");
    };

    const int wm = (wid & 3) << 5;
    const int wn = (wid >> 2) << 6;
    uint32_t a_off[2];
    #pragma unroll
    for (int im = 0; im < 2; im++)
        a_off[im] = ((wm + im*16 + (lane & 15))*AST + ((lane >> 4) << 3))*2;
    const uint32_t b_off = ((wn + ((lane >> 4) << 3) + (lane & 7))*BST
                           + (((lane >> 3) & 1) << 3))*2;
    const int gr0 = lane >> 2;
    const int cl0 = (lane & 3) << 1;

    load_B(0, 0);
    int buf = 0;

    #pragma unroll 1
    for (int w = 0; w < 5; w++) {
        float acc[2][8][4];
        #pragma unroll
        for (int im = 0; im < 2; im++)
            #pragma unroll
            for (int j = 0; j < 8; j++)
                #pragma unroll
                for (int q = 0; q < 4; q++) acc[im][j][q] = 0.f;

        #pragma unroll
        for (int g = 0; g < 4; g++) {
            int t = w*4 + g;
            if (t < 19) {
                load_B(t + 1, buf ^ 1);
                asm volatile("cp.async.wait_group 1;");
            } else {
                asm volatile("cp.async.wait_group 0;");
            }
            __syncthreads();
            const uint32_t a_s = sb + g*ABYTES;
            const uint32_t b_s = sb + AFULL + buf*BBYTES;
            #pragma unroll
            for (int ks = 0; ks < 4; ks++) {
                const uint32_t kh2 = (ks << 4)*2;
                uint32_t a[2][4], b[8][2];
                ldsm4(a_s + a_off[0] + kh2, a[0][0], a[0][1], a[0][2], a[0][3]);
                ldsm4(a_s + a_off[1] + kh2, a[1][0], a[1][1], a[1][2], a[1][3]);
                #pragma unroll
                for (int jp = 0; jp < 4; jp++)
                    ldsm4(b_s + b_off + jp*(16*BST*2) + kh2,
                          b[2*jp][0], b[2*jp][1], b[2*jp+1][0], b[2*jp+1][1]);
                #pragma unroll
                for (int im = 0; im < 2; im++)
                    #pragma unroll
                    for (int j = 0; j < 8; j++)
                        mma16816(acc[im][j], a[im], b[j]);
            }
            __syncthreads();
            buf ^= 1;
        }

        // epilogue for weight w (registers -> global; no smem touched)
        if (w < 2) {
            float* Cf = (float*)p.O[w];
            #pragma unroll
            for (int im = 0; im < 2; im++)
                #pragma unroll
                for (int half = 0; half < 2; half++) {
                    int gm = m0 + wm + im*16 + gr0 + half*8;
                    if (gm >= M) continue;
                    #pragma unroll
                    for (int j = 0; j < 8; j++) {
                        int col = wn + (j << 3) + cl0;
                        *(float2*)(Cf + (size_t)gm*256 + col) =
                            make_float2(acc[im][j][half*2], acc[im][j][half*2+1]);
                    }
                }
        } else {
            __half* Ch = (__half*)p.O[w];
            #pragma unroll
            for (int im = 0; im < 2; im++)
                #pragma unroll
                for (int half = 0; half < 2; half++) {
                    int gm = m0 + wm + im*16 + gr0 + half*8;
                    if (gm >= M) continue;
                    #pragma unroll
                    for (int j = 0; j < 8; j++) {
                        int col = wn + (j << 3) + cl0;
                        *(__half2*)(Ch + (size_t)gm*256 + col) =
                            __float22half2_rn(make_float2(acc[im][j][half*2], acc[im][j][half*2+1]));
                    }
                }
        }
    }
}

// ------------------------- edge GEMM (fused epilogue) -----------------------
__global__ __launch_bounds__(512)
void edge_mma_k(const __half* __restrict__ A,
                const __half* __restrict__ Bt, __half* __restrict__ C,
                const int* __restrict__ src, const int* __restrict__ dst,
                const float* __restrict__ gs, const float* __restrict__ gd,
                const float* __restrict__ af, const float* __restrict__ ab,
                float* __restrict__ logf, float* __restrict__ logb,
                float* __restrict__ mf, float* __restrict__ mb,
                float* __restrict__ cse, float* __restrict__ cqe)
{
    extern __shared__ __align__(16) char smem[];
    const uint32_t sb = s2u(smem);
    const int tid = threadIdx.x, wid = tid >> 5, lane = tid & 31;
    const int m0 = blockIdx.x * BM;

    auto load_chunk = [&](int g, int buf) {
        const uint32_t a_s = sb + buf*BUFB;
        const uint32_t b_s = a_s + ABYTES;
        #pragma unroll
        for (int i = 0; i < 2; i++) {
            int v = tid + (i << 9); int r = v >> 3, c16 = v & 7;
            cp_async16(a_s + (r*AST + (c16 << 3))*2,
                       A + (size_t)(m0 + r)*256 + (g << 6) + (c16 << 3));
        }
        #pragma unroll
        for (int i = 0; i < 4; i++) {
            int v = tid + (i << 9); int r = v >> 3, c16 = v & 7;
            cp_async16(b_s + (r*BST + (c16 << 3))*2, Bt + r*WK + (g << 6) + (c16 << 3));
        }
        asm volatile("cp.async.commit_group;");
    };

    const int wm = (wid & 3) << 5;
    const int wn = (wid >> 2) << 6;
    uint32_t a_off[2];
    #pragma unroll
    for (int im = 0; im < 2; im++)
        a_off[im] = ((wm + im*16 + (lane & 15))*AST + ((lane >> 4) << 3))*2;
    const uint32_t b_off = ((wn + ((lane >> 4) << 3) + (lane & 7))*BST
                           + (((lane >> 3) & 1) << 3))*2;

    float acc[2][8][4];
    #pragma unroll
    for (int im = 0; im < 2; im++)
        #pragma unroll
        for (int j = 0; j < 8; j++)
            #pragma unroll
            for (int q = 0; q < 4; q++) acc[im][j][q] = 0.f;

    load_chunk(0, 0);
    int buf = 0;
    for (int c = 0; c < 4; c++) {
        if (c < 3) {
            load_chunk(c + 1, buf ^ 1);
            asm volatile("cp.async.wait_group 1;");
        } else {
            asm volatile("cp.async.wait_group 0;");
        }
        __syncthreads();
        const uint32_t a_s = sb + buf*BUFB;
        const uint32_t b_s = a_s + ABYTES;
        #pragma unroll
        for (int ks = 0; ks < 4; ks++) {
            const uint32_t kh2 = (ks << 4)*2;
            uint32_t a[2][4], b[8][2];
            ldsm4(a_s + a_off[0] + kh2, a[0][0], a[0][1], a[0][2], a[0][3]);
            ldsm4(a_s + a_off[1] + kh2, a[1][0], a[1][1], a[1][2], a[1][3]);
            #pragma unroll
            for (int jp = 0; jp < 4; jp++)
                ldsm4(b_s + b_off + jp*(16*BST*2) + kh2,
                      b[2*jp][0], b[2*jp][1], b[2*jp+1][0], b[2*jp+1][1]);
            #pragma unroll
            for (int im = 0; im < 2; im++)
                #pragma unroll
                for (int j = 0; j < 8; j++)
                    mma16816(acc[im][j], a[im], b[j]);
        }
        __syncthreads();
        buf ^= 1;
    }

    const int gr0 = lane >> 2;
    const int cl0 = (lane & 3) << 1;

    float* sred = (float*)smem;
    for (int i = tid; i < 768; i += 512) sred[i] = 0.f;
    __syncthreads();

    float cs[16], cq[16];
    #pragma unroll
    for (int q = 0; q < 16; q++) { cs[q] = 0.f; cq[q] = 0.f; }

    #pragma unroll
    for (int im = 0; im < 2; im++)
        #pragma unroll
        for (int half = 0; half < 2; half++) {
            int rloc = wm + im*16 + gr0 + half*8;
            int gm = m0 + rloc;
            int s = src[gm], d = dst[gm];
            float pf = 0.f, pb = 0.f;
            #pragma unroll
            for (int j = 0; j < 8; j++) {
                int col = wn + (j << 3) + cl0;
                float2 o = make_float2(acc[im][j][half*2], acc[im][j][half*2+1]);
                float2 x = *(const float2*)(gs + (size_t)s*256 + col);
                float2 y = *(const float2*)(gd + (size_t)d*256 + col);
                o.x += x.x + y.x; o.y += x.y + y.y;
                *(__half2*)(C + (size_t)gm*256 + col) = __float22half2_rn(o);
                pf += o.x*__ldg(af+col) + o.y*__ldg(af+col+1);
                pb += o.x*__ldg(ab+col) + o.y*__ldg(ab+col+1);
                cs[j*2]   += o.x; cs[j*2+1] += o.y;
                cq[j*2]   += o.x*o.x; cq[j*2+1] += o.y*o.y;
            }
            pf += __shfl_xor_sync(0xFFFFFFFFu, pf, 1);
            pf += __shfl_xor_sync(0xFFFFFFFFu, pf, 2);
            pb += __shfl_xor_sync(0xFFFFFFFFu, pb, 1);
            pb += __shfl_xor_sync(0xFFFFFFFFu, pb, 2);
            if ((lane & 3) == 0) {
                atomicAdd(&sred[rloc], pf);
                atomicAdd(&sred[128 + rloc], pb);
            }
        }
    #pragma unroll
    for (int q = 0; q < 16; q++) {
        cs[q] += __shfl_xor_sync(0xFFFFFFFFu, cs[q], 4);
        cs[q] += __shfl_xor_sync(0xFFFFFFFFu, cs[q], 8);
        cs[q] += __shfl_xor_sync(0xFFFFFFFFu, cs[q], 16);
        cq[q] += __shfl_xor_sync(0xFFFFFFFFu, cq[q], 4);
        cq[q] += __shfl_xor_sync(0xFFFFFFFFu, cq[q], 8);
        cq[q] += __shfl_xor_sync(0xFFFFFFFFu, cq[q], 16);
    }
    if (lane < 4) {
        #pragma unroll
        for (int j = 0; j < 8; j++) {
            int col = wn + (j << 3) + ((lane & 3) << 1);
            atomicAdd(&sred[256 + col],     cs[j*2]);
            atomicAdd(&sred[256 + col + 1], cs[j*2+1]);
            atomicAdd(&sred[512 + col],     cq[j*2]);
            atomicAdd(&sred[512 + col + 1], cq[j*2+1]);
        }
    }
    __syncthreads();
    if (tid < 128) {
        int gm = m0 + tid;
        float lf = sred[tid];       lf = lf > 0.f ? lf : 0.2f*lf;
        float lb = sred[128 + tid]; lb = lb > 0.f ? lb : 0.2f*lb;
        logf[gm] = lf; logb[gm] = lb;
        atomicMaxF(&mf[dst[gm]], lf);
        atomicMaxF(&mb[src[gm]], lb);
    } else if (tid < 384) {
        int col = tid - 128;
        atomicAdd(&cse[col], sred[256 + col]);
        atomicAdd(&cqe[col], sred[512 + col]);
    }
}

// ------------------------- prep / CSR ---------------------------------------
struct W6 { const float* p[6]; };

__global__ void prep_w_k(W6 w, __half* __restrict__ out) {
    long idx = (long)blockIdx.x * 256 + threadIdx.x;
    int k = (int)(idx % WK); long t = idx / WK;
    int n = (int)(t % 256);  t /= 256;
    int wi = (int)(t % 6);   int l = (int)(t / 6);
    out[idx] = __float2half(w.p[wi][((size_t)l * 256 + k) * 256 + n]);
}

__global__ void cvt_k(const float4* __restrict__ x, __half2* __restrict__ hi,
                      __half2* __restrict__ lo, int n4) {
    int i = blockIdx.x * blockDim.x + threadIdx.x;
    if (i >= n4) return;
    float4 v = x[i];
    __half h0 = __float2half(v.x), h1 = __float2half(v.y);
    __half h2 = __float2half(v.z), h3 = __float2half(v.w);
    hi[2*i]   = __halves2half2(h0, h1);
    hi[2*i+1] = __halves2half2(h2, h3);
    lo[2*i]   = __halves2half2(__float2half(v.x - __half2float(h0)),
                               __float2half(v.y - __half2float(h1)));
    lo[2*i+1] = __halves2half2(__float2half(v.z - __half2float(h2)),
                               __float2half(v.w - __half2float(h3)));
}

__global__ void cvt_e_k(const float4* __restrict__ x, __half2* __restrict__ hi, int n4) {
    int i = blockIdx.x * blockDim.x + threadIdx.x;
    if (i >= n4) return;
    float4 v = x[i];
    hi[2*i]   = __float22half2_rn(make_float2(v.x, v.y));
    hi[2*i+1] = __float22half2_rn(make_float2(v.z, v.w));
}

__global__ void zero_deg_k(int* df, int* db) {
    int i = blockIdx.x*blockDim.x + threadIdx.x;
    if (i < NN) { df[i] = 0; db[i] = 0; }
}
__global__ void hist_k(const int* __restrict__ src, const int* __restrict__ dst,
                       int* df, int* db) {
    int e = blockIdx.x*blockDim.x + threadIdx.x;
    if (e >= EE) return;
    atomicAdd(&df[dst[e]], 1);
    atomicAdd(&db[src[e]], 1);
}
__global__ void scan_k(const int* __restrict__ degf, const int* __restrict__ degb,
                       int* offf, int* offb) {
    __shared__ int s[1024];
    for (int arr = 0; arr < 2; arr++) {
        const int* deg = arr ? degb : degf;
        int* off = arr ? offb : offf;
        int carry = 0;
        if (threadIdx.x == 0) off[0] = 0;
        for (int base = 0; base < NN; base += 1024) {
            int i = base + threadIdx.x;
            s[threadIdx.x] = (i < NN) ? deg[i] : 0;
            __syncthreads();
            for (int d = 1; d < 1024; d <<= 1) {
                int t = (threadIdx.x >= d) ? s[threadIdx.x - d] : 0;
                __syncthreads();
                s[threadIdx.x] += t;
                __syncthreads();
            }
            if (i < NN) off[i+1] = carry + s[threadIdx.x];
            carry += s[1023];
            __syncthreads();
        }
    }
}
__global__ void curcpy_k(const int* offf, const int* offb, int* curf, int* curb) {
    int i = blockIdx.x*blockDim.x + threadIdx.x;
    if (i < NN) { curf[i] = offf[i]; curb[i] = offb[i]; }
}
__global__ void fill_k(const int* __restrict__ src, const int* __restrict__ dst,
                       int* curf, int* curb, int* idxf, int* idxb) {
    int e = blockIdx.x*blockDim.x + threadIdx.x;
    if (e >= EE) return;
    idxf[atomicAdd(&curf[dst[e]], 1)] = e;
    idxb[atomicAdd(&curb[src[e]], 1)] = e;
}

// ------------------------- per-layer small kernels --------------------------
__global__ void init_k(float* mf, float* mb, float* denf, float* denb, float* cols) {
    int i = blockIdx.x*blockDim.x + threadIdx.x;
    if (i < NN) { mf[i] = -INFINITY; mb[i] = -INFINITY; denf[i] = 0.f; denb[i] = 0.f; }
    if (i < 8*FF) cols[i] = 0.f;
}

// Combined: blocks [0,EXPB) do exp+den atomics; blocks [EXPB,..) do e-residual
// with inline BN finalize (scale/shift computed per block from raw col stats).
__global__ void exp_rese_k(
    const float* __restrict__ logf, const float* __restrict__ logb,
    const int* __restrict__ src, const int* __restrict__ dst,
    const float* __restrict__ mf, const float* __restrict__ mb,
    float* __restrict__ exf, float* __restrict__ exb,
    float* __restrict__ denf, float* __restrict__ denb,
    uint4* __restrict__ ehi, const uint4* __restrict__ etmp,
    const float* __restrict__ cse, const float* __restrict__ cqe,
    const float* __restrict__ gsc, const float* __restrict__ gsh,
    float4* __restrict__ outF, int writeF)
{
    __shared__ float sc[256], sh[256];
    int blk = blockIdx.x;
    if (blk < EXPB) {
        int i = blk*256 + threadIdx.x;
        if (i < EE) {
            int d = dst[i], s = src[i];
            float ef = expf(logf[i] - mf[d]);
            float eb = expf(logb[i] - mb[s]);
            exf[i] = ef; exb[i] = eb;
            atomicAdd(&denf[d], ef);
            atomicAdd(&denb[s], eb);
        }
        return;
    }
    blk -= EXPB;
    {
        int f = threadIdx.x;
        float mean = cse[f] * (1.0f/EE);
        float var  = cqe[f] * (1.0f/EE) - mean*mean;
        float s    = gsc[f] * rsqrtf(var + 1e-5f);
        sc[f] = s;
        sh[f] = gsh[f] - mean * s;
    }
    __syncthreads();
    int base = blk*1024 + threadIdx.x;
    #pragma unroll
    for (int k = 0; k < 4; k++) {
        int i = base + (k << 8);
        int c8 = i & 31;
        uint4 hv = ehi[i];
        uint4 xv = etmp[i];
        const __half2* hp = (const __half2*)&hv;
        const __half2* xp = (const __half2*)&xv;
        float r[8];
        #pragma unroll
        for (int q = 0; q < 4; q++) {
            float2 a = __half22float2(hp[q]);
            float2 b = __half22float2(xp[q]);
            int col = c8*8 + q*2;
            r[q*2]   = a.x + fmaxf(b.x*sc[col]   + sh[col],   0.f);
            r[q*2+1] = a.y + fmaxf(b.y*sc[col+1] + sh[col+1], 0.f);
        }
        uint4 ov;
        __half2* op = (__half2*)&ov;
        op[0] = __float22half2_rn(make_float2(r[0], r[1]));
        op[1] = __float22half2_rn(make_float2(r[2], r[3]));
        op[2] = __float22half2_rn(make_float2(r[4], r[5]));
        op[3] = __float22half2_rn(make_float2(r[6], r[7]));
        ehi[i] = ov;
        if (writeF) {
            outF[2*i]   = make_float4(r[0], r[1], r[2], r[3]);
            outF[2*i+1] = make_float4(r[4], r[5], r[6], r[7]);
        }
    }
}

// h residual: hi/lo carry, fp16 htmp; inline BN finalize; fp32 out on last
__global__ void residual_h_k(__half2* hi, __half2* lo, const uint2* __restrict__ x,
                             const float* __restrict__ csh, const float* __restrict__ cqh,
                             const float* __restrict__ gsc, const float* __restrict__ gsh,
                             float4* __restrict__ outF, int writeF) {
    __shared__ float sc[256], sh[256];
    {
        int f = threadIdx.x;
        float mean = csh[f] * (1.0f/NN);
        float var  = cqh[f] * (1.0f/NN) - mean*mean;
        float s    = gsc[f] * rsqrtf(var + 1e-5f);
        sc[f] = s;
        sh[f] = gsh[f] - mean * s;
    }
    __syncthreads();
    int base = blockIdx.x*1024 + threadIdx.x;
    #pragma unroll
    for (int k = 0; k < 4; k++) {
        int i = base + (k << 8);
        int c4 = i & 63;
        __half2 a0 = hi[2*i], a1 = hi[2*i+1], b0 = lo[2*i], b1 = lo[2*i+1];
        float4 bse;
        bse.x = __half2float(a0.x) + __half2float(b0.x);
        bse.y = __half2float(a0.y) + __half2float(b0.y);
        bse.z = __half2float(a1.x) + __half2float(b1.x);
        bse.w = __half2float(a1.y) + __half2float(b1.y);
        uint2 xu = x[i];
        float2 x0 = __half22float2(*(const __half2*)&xu.x);
        float2 x1 = __half22float2(*(const __half2*)&xu.y);
        int col = c4*4;
        float4 r;
        r.x = bse.x + fmaxf(x0.x*sc[col]   + sh[col],   0.f);
        r.y = bse.y + fmaxf(x0.y*sc[col+1] + sh[col+1], 0.f);
        r.z = bse.z + fmaxf(x1.x*sc[col+2] + sh[col+2], 0.f);
        r.w = bse.w + fmaxf(x1.y*sc[col+3] + sh[col+3], 0.f);
        __half h0 = __float2half(r.x), h1 = __float2half(r.y);
        __half h2 = __float2half(r.z), h3 = __float2half(r.w);
        hi[2*i]   = __halves2half2(h0, h1);
        hi[2*i+1] = __halves2half2(h2, h3);
        lo[2*i]   = __halves2half2(__float2half(r.x - __half2float(h0)),
                                   __float2half(r.y - __half2float(h1)));
        lo[2*i+1] = __halves2half2(__float2half(r.z - __half2float(h2)),
                                   __float2half(r.w - __half2float(h3)));
        if (writeF) outF[i] = r;
    }
}

// CSR gather aggregation + node update + BN stats (fp16, 8B loads).
__global__ void gather_node_k(
    const int* __restrict__ offf, const int* __restrict__ idxf,
    const int* __restrict__ offb, const int* __restrict__ idxb,
    const int* __restrict__ src, const int* __restrict__ dst,
    const float* __restrict__ exf, const float* __restrict__ denf,
    const float* __restrict__ exb, const float* __restrict__ denb,
    const uint2* __restrict__ hWf, const uint2* __restrict__ hWb,
    const uint2* __restrict__ hself, uint2* __restrict__ htmp,
    float* __restrict__ colsum, float* __restrict__ colsumsq) {
    __shared__ float4 scs[256], scq[256];
    const int sub = threadIdx.x >> 6, c = threadIdx.x & 63;
    float4 csum = make_float4(0,0,0,0), csq = make_float4(0,0,0,0);
    #pragma unroll 1
    for (int nn = 0; nn < 8; nn++) {
        int node = blockIdx.x*32 + sub*8 + nn;
        if (node >= NN) break;
        float invf = 1.f/(denf[node] + 1e-9f);
        float invb = 1.f/(denb[node] + 1e-9f);
        uint2 su = hself[(size_t)node*64 + c];
        float2 s0 = __half22float2(*(const __half2*)&su.x);
        float2 s1 = __half22float2(*(const __half2*)&su.y);
        float4 acc = make_float4(s0.x, s0.y, s1.x, s1.y);
        int e0 = offf[node], e1 = offf[node+1];
        for (int i = e0; i < e1; i++) {
            int e = idxf[i];
            float a = exf[e]*invf;
            uint2 u = hWf[(size_t)src[e]*64 + c];
            float2 v0 = __half22float2(*(const __half2*)&u.x);
            float2 v1 = __half22float2(*(const __half2*)&u.y);
            acc.x += a*v0.x; acc.y += a*v0.y; acc.z += a*v1.x; acc.w += a*v1.y;
        }
        e0 = offb[node]; e1 = offb[node+1];
        for (int i = e0; i < e1; i++) {
            int e = idxb[i];
            float a = exb[e]*invb;
            uint2 u = hWb[(size_t)dst[e]*64 + c];
            float2 v0 = __half22float2(*(const __half2*)&u.x);
            float2 v1 = __half22float2(*(const __half2*)&u.y);
            acc.x += a*v0.x; acc.y += a*v0.y; acc.z += a*v1.x; acc.w += a*v1.y;
        }
        uint2 ou;
        *(__half2*)&ou.x = __float22half2_rn(make_float2(acc.x, acc.y));
        *(__half2*)&ou.y = __float22half2_rn(make_float2(acc.z, acc.w));
        htmp[(size_t)node*64 + c] = ou;
        csum.x += acc.x; csum.y += acc.y; csum.z += acc.z; csum.w += acc.w;
        csq.x += acc.x*acc.x; csq.y += acc.y*acc.y; csq.z += acc.z*acc.z; csq.w += acc.w*acc.w;
    }
    scs[threadIdx.x] = csum; scq[threadIdx.x] = csq;
    __syncthreads();
    if (sub == 0) {
        float4 s = scs[c], q = scq[c];
        #pragma unroll
        for (int k = 1; k < 4; k++) {
            float4 t = scs[k*64 + c], u = scq[k*64 + c];
            s.x += t.x; s.y += t.y; s.z += t.z; s.w += t.w;
            q.x += u.x; q.y += u.y; q.z += u.z; q.w += u.w;
        }
        atomicAdd(&colsum[c*4+0], s.x); atomicAdd(&colsum[c*4+1], s.y);
        atomicAdd(&colsum[c*4+2], s.z); atomicAdd(&colsum[c*4+3], s.w);
        atomicAdd(&colsumsq[c*4+0], q.x); atomicAdd(&colsumsq[c*4+1], q.y);
        atomicAdd(&colsumsq[c*4+2], q.z); atomicAdd(&colsumsq[c*4+3], q.w);
    }
}

// ------------------------- host orchestration ------------------------------
static float* symF(const void* s) { void* p = nullptr; cudaGetSymbolAddress(&p, s); return (float*)p; }
static int*   symI(const void* s) { void* p = nullptr; cudaGetSymbolAddress(&p, s); return (int*)p; }
static __half* symH(const void* s) { void* p = nullptr; cudaGetSymbolAddress(&p, s); return (__half*)p; }

extern "C" void kernel_launch(void* const* d_in, const int* in_sizes, int n_in,
                              void* d_out, int out_size) {
    const float* h0   = (const float*)d_in[0];
    const float* e0   = (const float*)d_in[1];
    const int*   src  = (const int*)d_in[2];
    const int*   dst  = (const int*)d_in[3];
    const float* We   = (const float*)d_in[4];
    const float* Ws   = (const float*)d_in[5];
    const float* Wd   = (const float*)d_in[6];
    const float* Wse  = (const float*)d_in[7];
    const float* Wf   = (const float*)d_in[8];
    const float* Wb   = (const float*)d_in[9];
    const float* attf = (const float*)d_in[10];
    const float* attb = (const float*)d_in[11];
    const float* ge   = (const float*)d_in[12];
    const float* be   = (const float*)d_in[13];
    const float* gh   = (const float*)d_in[14];
    const float* bh   = (const float*)d_in[15];

    __half* etmp = symH(g_etmp);
    float* hW    = symF(g_hW);
    __half* hWh  = symH(g_hWh);
    __half* htmp = symH(g_htmp);
    float* logf = symF(g_logf);
    float* logb = symF(g_logb);
    float* exf  = symF(g_exf);
    float* exb  = symF(g_exb);
    float* mf   = symF(g_mf);
    float* mb   = symF(g_mb);
    float* denf = symF(g_denf);
    float* denb = symF(g_denb);
    float* cols = symF(g_cols);
    __half* hhi = symH(g_hhi);
    __half* hlo = symH(g_hlo);
    __half* ehi = symH(g_ehi);
    __half* Wt  = symH(g_Wt);
    int* degf = symI(g_degf);  int* degb = symI(g_degb);
    int* offf = symI(g_offf);  int* offb = symI(g_offb);
    int* idxf = symI(g_idxf);  int* idxb = symI(g_idxb);

    float* hWs = hW;           float* hWd = hW + NF;
    __half* hse16 = hWh;       __half* hWf16 = hWh + NF;
    __half* hWb16 = hWh + 2*NF;

    float* cse = cols;         float* cqe = cols + FF;
    float* csh = cols + 4*FF;  float* cqh = cols + 5*FF;

    float* outH; float* outE;
    float* dumpF = symF(g_dumpE);
    if (out_size >= NF + EF)      { outH = (float*)d_out; outE = (float*)d_out + NF; }
    else if (out_size == EF)      { outE = (float*)d_out; outH = dumpF; }
    else                          { outH = (float*)d_out; outE = dumpF; }

    cudaFuncSetAttribute(node_mma_all_k, cudaFuncAttributeMaxDynamicSharedMemorySize, SMEM_NODE);
    cudaFuncSetAttribute(edge_mma_k,     cudaFuncAttributeMaxDynamicSharedMemorySize, SMEMB);

    // weights (once)
    W6 w6; w6.p[0] = We; w6.p[1] = Ws; w6.p[2] = Wd; w6.p[3] = Wse; w6.p[4] = Wf; w6.p[5] = Wb;
    prep_w_k<<<(LL*6*WSZ)/256, 256>>>(w6, Wt);

    // inputs (once): h -> hi/lo; e -> hi only
    cvt_k<<<(NF/4 + 255)/256, 256>>>((const float4*)h0, (__half2*)hhi, (__half2*)hlo, NF/4);
    cvt_e_k<<<(EF/4 + 255)/256, 256>>>((const float4*)e0, (__half2*)ehi, EF/4);

    // CSR (once per launch)
    zero_deg_k<<<(NN+255)/256, 256>>>(degf, degb);
    hist_k<<<(EE+255)/256, 256>>>(src, dst, degf, degb);
    scan_k<<<1, 1024>>>(degf, degb, offf, offb);
    curcpy_k<<<(NN+255)/256, 256>>>(offf, offb, degf, degb);
    fill_k<<<(EE+255)/256, 256>>>(src, dst, degf, degb, idxf, idxb);

    for (int l = 0; l < LL; l++) {
        __half* WtL = Wt + (size_t)l * 6 * WSZ;
        int last = (l == LL-1);

        init_k<<<(NN + 255)/256, 256>>>(mf, mb, denf, denb, cols);

        // fused node GEMMs (A-resident): {Ws,Wd} fp32; {Wself,Wf,Wb} fp16
        O5h p5;
        p5.O[0] = hWs; p5.O[1] = hWd; p5.O[2] = hse16; p5.O[3] = hWf16; p5.O[4] = hWb16;
        node_mma_all_k<<<(NN + BM - 1)/BM, 512, SMEM_NODE>>>(hhi, WtL, p5, NN);

        // edge GEMM + fused gather/logits/max/BN-stats, fp16 etmp out
        edge_mma_k<<<EE/BM, 512, SMEMB>>>(ehi, WtL, etmp, src, dst, hWs, hWd,
                                          attf + l*FF, attb + l*FF,
                                          logf, logb, mf, mb, cse, cqe);

        // combined exp (+den) and e-residual (inline BN finalize)
        exp_rese_k<<<EXPB + RESEB, 256>>>(logf, logb, src, dst, mf, mb,
                                          exf, exb, denf, denb,
                                          (uint4*)ehi, (const uint4*)etmp,
                                          cse, cqe, ge + l*FF, be + l*FF,
                                          (float4*)outE, last);

        // attention aggregation (CSR gather, fp16 8B loads) + node update + BN stats
        gather_node_k<<<(NN + 31)/32, 256>>>(offf, idxf, offb, idxb, src, dst,
                                             exf, denf, exb, denb,
                                             (const uint2*)hWf16, (const uint2*)hWb16,
                                             (const uint2*)hse16, (uint2*)htmp, csh, cqh);

        // h residual (hi/lo carry, fp16 htmp, inline BN finalize)
        residual_h_k<<<RESHB, 256>>>((__half2*)hhi, (__half2*)hlo,
                                     (const uint2*)htmp, csh, cqh,
                                     gh + l*FF, bh + l*FF,
                                     (float4*)outH, last);
    }
}